// round 1
// baseline (speedup 1.0000x reference)
#include <cuda_runtime.h>
#include <math.h>

// Problem constants
#define BATCH 64
#define SEQ   256
#define BT    16384      // BATCH*SEQ
#define CDIM  384
#define NH    6
#define HD    64
#define QKVN  1152       // 3*CDIM

// ---------------- scratch (static device globals; no allocation) ------------
__device__ float g_h   [BT * CDIM];
__device__ float g_qkv [BT * QKVN];
__device__ float g_attn[BT * CDIM];
__device__ float g_x2  [BT * CDIM];
__device__ float g_h2  [BT * CDIM];
__device__ float g_f1  [BT * CDIM];
__device__ float g_wqkv[CDIM * QKVN];
__device__ float g_bqkv[QKVN];

// ---------------- repack per-head Wq/Wk/Wv -> [C, 3C] GEMM weight -----------
// Wq is [H, C, D]; target Wqkv[c][h*64+d] (cols 0..383 q, 384..767 k, 768..1151 v)
__global__ void repack_kernel(const float* __restrict__ Wq,
                              const float* __restrict__ Wk,
                              const float* __restrict__ Wv,
                              const float* __restrict__ bq,
                              const float* __restrict__ bk,
                              const float* __restrict__ bv,
                              float* __restrict__ Wqkv,
                              float* __restrict__ bqkv) {
    int idx = blockIdx.x * blockDim.x + threadIdx.x;
    if (idx < CDIM * CDIM) {
        int h = idx / (CDIM * HD);
        int rem = idx - h * (CDIM * HD);
        int c = rem / HD;
        int d = rem - c * HD;
        int col = h * HD + d;
        Wqkv[c * QKVN + col]              = Wq[idx];
        Wqkv[c * QKVN + CDIM + col]       = Wk[idx];
        Wqkv[c * QKVN + 2 * CDIM + col]   = Wv[idx];
    }
    if (idx < CDIM) {
        // bq is [H, D] flattened: element idx maps to col idx directly
        bqkv[idx]            = bq[idx];
        bqkv[CDIM + idx]     = bk[idx];
        bqkv[2 * CDIM + idx] = bv[idx];
    }
}

// ---------------- LayerNorm: one block per row of 384 -----------------------
__global__ __launch_bounds__(128) void ln_kernel(const float* __restrict__ x,
                                                 const float* __restrict__ g,
                                                 const float* __restrict__ b,
                                                 float* __restrict__ out) {
    __shared__ float red1[4];
    __shared__ float red2[4];
    int row = blockIdx.x;
    int tid = threadIdx.x;
    const float* xr = x + (size_t)row * CDIM;

    float v0 = xr[tid], v1 = xr[tid + 128], v2 = xr[tid + 256];
    float s = v0 + v1 + v2;
    #pragma unroll
    for (int o = 16; o > 0; o >>= 1) s += __shfl_xor_sync(0xFFFFFFFFu, s, o);
    if ((tid & 31) == 0) red1[tid >> 5] = s;
    __syncthreads();
    float mu = (red1[0] + red1[1] + red1[2] + red1[3]) * (1.0f / CDIM);

    float d0 = v0 - mu, d1 = v1 - mu, d2 = v2 - mu;
    float sq = d0 * d0 + d1 * d1 + d2 * d2;
    #pragma unroll
    for (int o = 16; o > 0; o >>= 1) sq += __shfl_xor_sync(0xFFFFFFFFu, sq, o);
    if ((tid & 31) == 0) red2[tid >> 5] = sq;
    __syncthreads();
    float var = (red2[0] + red2[1] + red2[2] + red2[3]) * (1.0f / CDIM);
    float rs = rsqrtf(var + 1e-5f);

    float* orow = out + (size_t)row * CDIM;
    orow[tid]       = d0 * rs * g[tid]       + b[tid];
    orow[tid + 128] = d1 * rs * g[tid + 128] + b[tid + 128];
    orow[tid + 256] = d2 * rs * g[tid + 256] + b[tid + 256];
}

// ---------------- SGEMM: C = A[M,K] @ B[K,N] + bias (+resid)(+relu) ---------
// BM=BN=64, BK=16, 256 threads, 4x4 per thread. M%64==0, N%64==0, K%16==0.
template <bool RELU, bool RESID>
__global__ __launch_bounds__(256) void gemm64_kernel(
    int M, int N, int K,
    const float* __restrict__ A, const float* __restrict__ Bm,
    const float* __restrict__ bias, const float* __restrict__ resid,
    float* __restrict__ Cout) {
    __shared__ float As[16][68];   // padded, stored transposed: As[k][m]
    __shared__ float Bs[16][64];

    int tid = threadIdx.x;
    int bm = blockIdx.y * 64;
    int bn = blockIdx.x * 64;

    int ar = tid >> 2;            // 0..63
    int ac = (tid & 3) * 4;       // 0,4,8,12
    int br = tid >> 4;            // 0..15
    int bc = (tid & 15) * 4;      // 0..60
    int ty = tid >> 4;            // 0..15 (row group)
    int tx = tid & 15;            // 0..15 (col group)

    const float* Aptr = A + (size_t)(bm + ar) * K + ac;
    const float* Bptr = Bm + (size_t)br * N + bn + bc;

    float acc[4][4];
    #pragma unroll
    for (int i = 0; i < 4; i++)
        #pragma unroll
        for (int j = 0; j < 4; j++) acc[i][j] = 0.0f;

    for (int k0 = 0; k0 < K; k0 += 16) {
        float4 av = *(const float4*)(Aptr + k0);
        As[ac + 0][ar] = av.x;
        As[ac + 1][ar] = av.y;
        As[ac + 2][ar] = av.z;
        As[ac + 3][ar] = av.w;
        float4 bv = *(const float4*)(Bptr + (size_t)k0 * N);
        *(float4*)&Bs[br][bc] = bv;
        __syncthreads();

        #pragma unroll
        for (int k = 0; k < 16; k++) {
            float4 a4 = *(const float4*)&As[k][ty * 4];
            float4 b4 = *(const float4*)&Bs[k][tx * 4];
            acc[0][0] += a4.x * b4.x; acc[0][1] += a4.x * b4.y;
            acc[0][2] += a4.x * b4.z; acc[0][3] += a4.x * b4.w;
            acc[1][0] += a4.y * b4.x; acc[1][1] += a4.y * b4.y;
            acc[1][2] += a4.y * b4.z; acc[1][3] += a4.y * b4.w;
            acc[2][0] += a4.z * b4.x; acc[2][1] += a4.z * b4.y;
            acc[2][2] += a4.z * b4.z; acc[2][3] += a4.z * b4.w;
            acc[3][0] += a4.w * b4.x; acc[3][1] += a4.w * b4.y;
            acc[3][2] += a4.w * b4.z; acc[3][3] += a4.w * b4.w;
        }
        __syncthreads();
    }

    #pragma unroll
    for (int i = 0; i < 4; i++) {
        int row = bm + ty * 4 + i;
        #pragma unroll
        for (int j = 0; j < 4; j++) {
            int col = bn + tx * 4 + j;
            float c = acc[i][j] + bias[col];
            if (RESID) c += resid[(size_t)row * N + col];
            if (RELU) c = fmaxf(c, 0.0f);
            Cout[(size_t)row * N + col] = c;
        }
    }
}

// ---------------- causal attention: one block per (b, h) --------------------
// 256 threads; thread t = query row. K,V in dynamic smem (2 * 256*64 floats).
// Online softmax; q + accumulator in registers.
__global__ __launch_bounds__(256, 1) void attn_kernel(
    const float* __restrict__ qkv, float* __restrict__ out) {
    extern __shared__ float smem[];
    float4* K4 = (float4*)smem;                    // [256][16] float4
    float4* V4 = (float4*)(smem + SEQ * HD);       // [256][16] float4

    int bh = blockIdx.x;
    int b = bh / NH;
    int h = bh - b * NH;
    const float* base = qkv + (size_t)b * SEQ * QKVN;
    int hoff = h * HD;

    // cooperative load of K and V tiles (16384 floats each)
    for (int i = threadIdx.x; i < SEQ * (HD / 4); i += 256) {
        int s = i >> 4;          // 0..255
        int d4 = i & 15;         // 0..15
        const float* rowp = base + (size_t)s * QKVN;
        K4[i] = *(const float4*)(rowp + CDIM + hoff + d4 * 4);
        V4[i] = *(const float4*)(rowp + 2 * CDIM + hoff + d4 * 4);
    }
    __syncthreads();

    int t = threadIdx.x;
    float4 q4[16];
    {
        const float* qp = base + (size_t)t * QKVN + hoff;
        #pragma unroll
        for (int i = 0; i < 16; i++) q4[i] = *(const float4*)(qp + i * 4);
    }

    const float scale = rsqrtf((float)CDIM);
    float m = -INFINITY;
    float l = 0.0f;
    float4 a4[16];
    #pragma unroll
    for (int i = 0; i < 16; i++) a4[i] = make_float4(0.f, 0.f, 0.f, 0.f);

    for (int s = 0; s <= t; s++) {
        float dot = 0.0f;
        #pragma unroll
        for (int i = 0; i < 16; i++) {
            float4 kk = K4[s * 16 + i];
            dot += q4[i].x * kk.x + q4[i].y * kk.y + q4[i].z * kk.z + q4[i].w * kk.w;
        }
        dot *= scale;
        float mnew = fmaxf(m, dot);
        float corr = __expf(m - mnew);   // exp(-inf)=0 on first iter
        float p = __expf(dot - mnew);
        l = l * corr + p;
        #pragma unroll
        for (int i = 0; i < 16; i++) {
            float4 vv = V4[s * 16 + i];
            a4[i].x = a4[i].x * corr + p * vv.x;
            a4[i].y = a4[i].y * corr + p * vv.y;
            a4[i].z = a4[i].z * corr + p * vv.z;
            a4[i].w = a4[i].w * corr + p * vv.w;
        }
        m = mnew;
    }

    float inv = 1.0f / l;
    float* op = out + ((size_t)(b * SEQ + t)) * CDIM + hoff;
    #pragma unroll
    for (int i = 0; i < 16; i++) {
        float4 r = a4[i];
        r.x *= inv; r.y *= inv; r.z *= inv; r.w *= inv;
        *(float4*)(op + i * 4) = r;
    }
}

// ---------------- launch ----------------------------------------------------
extern "C" void kernel_launch(void* const* d_in, const int* in_sizes, int n_in,
                              void* d_out, int out_size) {
    const float* x     = (const float*)d_in[0];
    const float* Wq    = (const float*)d_in[1];
    const float* bq    = (const float*)d_in[2];
    const float* Wk    = (const float*)d_in[3];
    const float* bk    = (const float*)d_in[4];
    const float* Wv    = (const float*)d_in[5];
    const float* bv    = (const float*)d_in[6];
    const float* Wp    = (const float*)d_in[7];
    const float* bp    = (const float*)d_in[8];
    const float* W1    = (const float*)d_in[9];
    const float* b1    = (const float*)d_in[10];
    const float* W2    = (const float*)d_in[11];
    const float* b2    = (const float*)d_in[12];
    const float* ln1g  = (const float*)d_in[13];
    const float* ln1b  = (const float*)d_in[14];
    const float* ln2g  = (const float*)d_in[15];
    const float* ln2b  = (const float*)d_in[16];

    float *h, *qkv, *attn, *x2, *h2, *f1, *wqkv, *bqkv;
    cudaGetSymbolAddress((void**)&h,    g_h);
    cudaGetSymbolAddress((void**)&qkv,  g_qkv);
    cudaGetSymbolAddress((void**)&attn, g_attn);
    cudaGetSymbolAddress((void**)&x2,   g_x2);
    cudaGetSymbolAddress((void**)&h2,   g_h2);
    cudaGetSymbolAddress((void**)&f1,   g_f1);
    cudaGetSymbolAddress((void**)&wqkv, g_wqkv);
    cudaGetSymbolAddress((void**)&bqkv, g_bqkv);

    cudaFuncSetAttribute(attn_kernel,
                         cudaFuncAttributeMaxDynamicSharedMemorySize,
                         2 * SEQ * HD * (int)sizeof(float));

    // 1. repack per-head QKV weights into one [C, 3C] matrix
    repack_kernel<<<(CDIM * CDIM + 255) / 256, 256>>>(Wq, Wk, Wv, bq, bk, bv,
                                                      wqkv, bqkv);
    // 2. LN1
    ln_kernel<<<BT, 128>>>(x, ln1g, ln1b, h);
    // 3. fused QKV projection: [16384,384] @ [384,1152]
    {
        dim3 grid(QKVN / 64, BT / 64);
        gemm64_kernel<false, false><<<grid, 256>>>(BT, QKVN, CDIM,
                                                   h, wqkv, bqkv, nullptr, qkv);
    }
    // 4. causal attention per (b,h)
    attn_kernel<<<BATCH * NH, 256, 2 * SEQ * HD * (int)sizeof(float)>>>(qkv, attn);
    // 5. output projection + residual: x2 = x + attn @ Wp + bp
    {
        dim3 grid(CDIM / 64, BT / 64);
        gemm64_kernel<false, true><<<grid, 256>>>(BT, CDIM, CDIM,
                                                  attn, Wp, bp, x, x2);
        // 6. LN2
        ln_kernel<<<BT, 128>>>(x2, ln2g, ln2b, h2);
        // 7. FF1 with ReLU
        gemm64_kernel<true, false><<<grid, 256>>>(BT, CDIM, CDIM,
                                                  h2, W1, b1, nullptr, f1);
        // 8. FF2 + residual -> out
        gemm64_kernel<false, true><<<grid, 256>>>(BT, CDIM, CDIM,
                                                  f1, W2, b2, x2, (float*)d_out);
    }
}

// round 2
// speedup vs baseline: 2.2293x; 2.2293x over previous
#include <cuda_runtime.h>
#include <math.h>

// Problem constants
#define BATCH 64
#define SEQ   256
#define BT    16384      // BATCH*SEQ
#define CDIM  384
#define NH    6
#define HD    64
#define QKVN  1152       // 3*CDIM

// ---------------- scratch (static device globals; no allocation) ------------
__device__ float g_h   [BT * CDIM];
__device__ float g_qkv [BT * QKVN];
__device__ float g_attn[BT * CDIM];
__device__ float g_x2  [BT * CDIM];
__device__ float g_h2  [BT * CDIM];
__device__ float g_f1  [BT * CDIM];
__device__ float g_wqkv[CDIM * QKVN];
__device__ float g_bqkv[QKVN];

// ---------------- repack per-head Wq/Wk/Wv -> [C, 3C] GEMM weight -----------
__global__ void repack_kernel(const float* __restrict__ Wq,
                              const float* __restrict__ Wk,
                              const float* __restrict__ Wv,
                              const float* __restrict__ bq,
                              const float* __restrict__ bk,
                              const float* __restrict__ bv,
                              float* __restrict__ Wqkv,
                              float* __restrict__ bqkv) {
    int idx = blockIdx.x * blockDim.x + threadIdx.x;
    if (idx < CDIM * CDIM) {
        int h = idx / (CDIM * HD);
        int rem = idx - h * (CDIM * HD);
        int c = rem / HD;
        int d = rem - c * HD;
        int col = h * HD + d;
        Wqkv[c * QKVN + col]            = Wq[idx];
        Wqkv[c * QKVN + CDIM + col]     = Wk[idx];
        Wqkv[c * QKVN + 2 * CDIM + col] = Wv[idx];
    }
    if (idx < CDIM) {
        bqkv[idx]            = bq[idx];
        bqkv[CDIM + idx]     = bk[idx];
        bqkv[2 * CDIM + idx] = bv[idx];
    }
}

// ---------------- LayerNorm: one block per row of 384 -----------------------
__global__ __launch_bounds__(128) void ln_kernel(const float* __restrict__ x,
                                                 const float* __restrict__ g,
                                                 const float* __restrict__ b,
                                                 float* __restrict__ out) {
    __shared__ float red1[4];
    __shared__ float red2[4];
    int row = blockIdx.x;
    int tid = threadIdx.x;
    const float* xr = x + (size_t)row * CDIM;

    float v0 = xr[tid], v1 = xr[tid + 128], v2 = xr[tid + 256];
    float s = v0 + v1 + v2;
    #pragma unroll
    for (int o = 16; o > 0; o >>= 1) s += __shfl_xor_sync(0xFFFFFFFFu, s, o);
    if ((tid & 31) == 0) red1[tid >> 5] = s;
    __syncthreads();
    float mu = (red1[0] + red1[1] + red1[2] + red1[3]) * (1.0f / CDIM);

    float d0 = v0 - mu, d1 = v1 - mu, d2 = v2 - mu;
    float sq = d0 * d0 + d1 * d1 + d2 * d2;
    #pragma unroll
    for (int o = 16; o > 0; o >>= 1) sq += __shfl_xor_sync(0xFFFFFFFFu, sq, o);
    if ((tid & 31) == 0) red2[tid >> 5] = sq;
    __syncthreads();
    float var = (red2[0] + red2[1] + red2[2] + red2[3]) * (1.0f / CDIM);
    float rs = rsqrtf(var + 1e-5f);

    float* orow = out + (size_t)row * CDIM;
    orow[tid]       = d0 * rs * g[tid]       + b[tid];
    orow[tid + 128] = d1 * rs * g[tid + 128] + b[tid + 128];
    orow[tid + 256] = d2 * rs * g[tid + 256] + b[tid + 256];
}

// ---------------- SGEMM 128x128, BK=16, 256 threads, 8x8/thread -------------
// C = A[M,K] @ B[K,N] + bias (+resid)(+relu). M%128==0, N%128==0, K%16==0.
template <bool RELU, bool RESID>
__global__ __launch_bounds__(256, 2) void gemm128_kernel(
    int M, int N, int K,
    const float* __restrict__ A, const float* __restrict__ Bm,
    const float* __restrict__ bias, const float* __restrict__ resid,
    float* __restrict__ Cout) {
    __shared__ float As[2][16][132];   // transposed, padded: As[k][m]
    __shared__ float Bs[2][16][128];

    int tid = threadIdx.x;
    int bm = blockIdx.y * 128;
    int bn = blockIdx.x * 128;
    int tx = tid & 15;
    int ty = tid >> 4;

    // A loads: 128 rows x 4 float4 each = 512 f4; thread does idx tid, tid+256
    int ar0 = tid >> 2;          // 0..63
    int ac0 = (tid & 3) * 4;     // 0,4,8,12
    const float* Ap = A + (size_t)(bm + ar0) * K + ac0;
    // B loads: 16 rows x 32 f4; thread does idx tid (rows 0..7), tid+256 (8..15)
    int br0 = tid >> 5;          // 0..7
    int bc0 = (tid & 31) * 4;    // 0..124
    const float* Bp = Bm + (size_t)br0 * N + bn + bc0;

    float4 pa0, pa1, pb0, pb1;

    // prefetch k0 = 0
    pa0 = *(const float4*)(Ap);
    pa1 = *(const float4*)(Ap + (size_t)64 * K);
    pb0 = *(const float4*)(Bp);
    pb1 = *(const float4*)(Bp + (size_t)8 * N);

    float acc[8][8];
    #pragma unroll
    for (int i = 0; i < 8; i++)
        #pragma unroll
        for (int j = 0; j < 8; j++) acc[i][j] = 0.0f;

    // store stage 0
    {
        As[0][ac0 + 0][ar0] = pa0.x; As[0][ac0 + 1][ar0] = pa0.y;
        As[0][ac0 + 2][ar0] = pa0.z; As[0][ac0 + 3][ar0] = pa0.w;
        As[0][ac0 + 0][ar0 + 64] = pa1.x; As[0][ac0 + 1][ar0 + 64] = pa1.y;
        As[0][ac0 + 2][ar0 + 64] = pa1.z; As[0][ac0 + 3][ar0 + 64] = pa1.w;
        *(float4*)&Bs[0][br0][bc0]     = pb0;
        *(float4*)&Bs[0][br0 + 8][bc0] = pb1;
    }
    __syncthreads();

    int sbuf = 0;
    for (int k0 = 16; k0 <= K; k0 += 16) {
        if (k0 < K) {
            pa0 = *(const float4*)(Ap + k0);
            pa1 = *(const float4*)(Ap + (size_t)64 * K + k0);
            pb0 = *(const float4*)(Bp + (size_t)k0 * N);
            pb1 = *(const float4*)(Bp + (size_t)(k0 + 8) * N);
        }
        // compute on sbuf
        #pragma unroll
        for (int k = 0; k < 16; k++) {
            float4 aLo = *(const float4*)&As[sbuf][k][ty * 4];
            float4 aHi = *(const float4*)&As[sbuf][k][64 + ty * 4];
            float4 bLo = *(const float4*)&Bs[sbuf][k][tx * 4];
            float4 bHi = *(const float4*)&Bs[sbuf][k][64 + tx * 4];
            float am[8] = {aLo.x, aLo.y, aLo.z, aLo.w, aHi.x, aHi.y, aHi.z, aHi.w};
            float bn_[8] = {bLo.x, bLo.y, bLo.z, bLo.w, bHi.x, bHi.y, bHi.z, bHi.w};
            #pragma unroll
            for (int i = 0; i < 8; i++)
                #pragma unroll
                for (int j = 0; j < 8; j++) acc[i][j] += am[i] * bn_[j];
        }
        if (k0 < K) {
            int ns = sbuf ^ 1;
            As[ns][ac0 + 0][ar0] = pa0.x; As[ns][ac0 + 1][ar0] = pa0.y;
            As[ns][ac0 + 2][ar0] = pa0.z; As[ns][ac0 + 3][ar0] = pa0.w;
            As[ns][ac0 + 0][ar0 + 64] = pa1.x; As[ns][ac0 + 1][ar0 + 64] = pa1.y;
            As[ns][ac0 + 2][ar0 + 64] = pa1.z; As[ns][ac0 + 3][ar0 + 64] = pa1.w;
            *(float4*)&Bs[ns][br0][bc0]     = pb0;
            *(float4*)&Bs[ns][br0 + 8][bc0] = pb1;
            __syncthreads();
            sbuf = ns;
        }
    }

    // epilogue
    #pragma unroll
    for (int rg = 0; rg < 2; rg++) {
        #pragma unroll
        for (int i = 0; i < 4; i++) {
            int row = bm + rg * 64 + ty * 4 + i;
            #pragma unroll
            for (int cg = 0; cg < 2; cg++) {
                int col = bn + cg * 64 + tx * 4;
                float4 bv = *(const float4*)(bias + col);
                float4 c;
                c.x = acc[rg * 4 + i][cg * 4 + 0] + bv.x;
                c.y = acc[rg * 4 + i][cg * 4 + 1] + bv.y;
                c.z = acc[rg * 4 + i][cg * 4 + 2] + bv.z;
                c.w = acc[rg * 4 + i][cg * 4 + 3] + bv.w;
                if (RESID) {
                    float4 r = *(const float4*)(resid + (size_t)row * N + col);
                    c.x += r.x; c.y += r.y; c.z += r.z; c.w += r.w;
                }
                if (RELU) {
                    c.x = fmaxf(c.x, 0.f); c.y = fmaxf(c.y, 0.f);
                    c.z = fmaxf(c.z, 0.f); c.w = fmaxf(c.w, 0.f);
                }
                *(float4*)(Cout + (size_t)row * N + col) = c;
            }
        }
    }
}

// ---------------- flash-tiled causal attention -------------------------------
// grid (4, B*H): block handles 64 query rows of one (b,h); s-tiles of 64.
// 256 threads as 16x16; each thread: 4x4 S-frag, 4x4 O-frag.
__global__ __launch_bounds__(256) void fattn_kernel(
    const float* __restrict__ qkv, float* __restrict__ out) {
    extern __shared__ float sm[];
    float (*Qs)[68] = (float(*)[68])(sm);              // [d][i], pre-scaled
    float (*Ks)[68] = (float(*)[68])(sm + 64 * 68);    // [d][j]
    float (*Vs)[68] = (float(*)[68])(sm + 2 * 64 * 68);// [j][d]
    float (*Ps)[68] = (float(*)[68])(sm + 3 * 64 * 68);// [j][i]

    int qt = blockIdx.x;
    int bh = blockIdx.y;
    int b = bh / NH;
    int h = bh - b * NH;
    const float* base = qkv + (size_t)b * SEQ * QKVN;
    int hoff = h * HD;
    int q0 = qt * 64;
    int tid = threadIdx.x;
    int tx = tid & 15;
    int ty = tid >> 4;
    const float scale = rsqrtf((float)CDIM);

    // load Q transposed + pre-scaled
    #pragma unroll
    for (int l = 0; l < 4; l++) {
        int idx = tid + l * 256;
        int i = idx >> 4, d4 = (idx & 15) * 4;
        float4 v = *(const float4*)(base + (size_t)(q0 + i) * QKVN + hoff + d4);
        Qs[d4 + 0][i] = v.x * scale; Qs[d4 + 1][i] = v.y * scale;
        Qs[d4 + 2][i] = v.z * scale; Qs[d4 + 3][i] = v.w * scale;
    }

    float m[4], lsum[4], o[4][4];
    #pragma unroll
    for (int i = 0; i < 4; i++) {
        m[i] = -INFINITY; lsum[i] = 0.0f;
        #pragma unroll
        for (int j = 0; j < 4; j++) o[i][j] = 0.0f;
    }

    for (int st = 0; st <= qt; st++) {
        int s0 = st * 64;
        __syncthreads();   // protect Ks/Vs (prev GEMM2 readers done)
        #pragma unroll
        for (int l = 0; l < 4; l++) {
            int idx = tid + l * 256;
            int j = idx >> 4, d4 = (idx & 15) * 4;
            const float* rp = base + (size_t)(s0 + j) * QKVN + hoff;
            float4 kv = *(const float4*)(rp + CDIM + d4);
            Ks[d4 + 0][j] = kv.x; Ks[d4 + 1][j] = kv.y;
            Ks[d4 + 2][j] = kv.z; Ks[d4 + 3][j] = kv.w;
            float4 vv = *(const float4*)(rp + 2 * CDIM + d4);
            *(float4*)&Vs[j][d4] = vv;
        }
        __syncthreads();

        // S = Q @ K^T  (4x4 per thread)
        float acc[4][4];
        #pragma unroll
        for (int i = 0; i < 4; i++)
            #pragma unroll
            for (int j = 0; j < 4; j++) acc[i][j] = 0.0f;
        #pragma unroll
        for (int d = 0; d < 64; d++) {
            float4 qv = *(const float4*)&Qs[d][ty * 4];
            float4 kv = *(const float4*)&Ks[d][tx * 4];
            float qa[4] = {qv.x, qv.y, qv.z, qv.w};
            float ka[4] = {kv.x, kv.y, kv.z, kv.w};
            #pragma unroll
            for (int i = 0; i < 4; i++)
                #pragma unroll
                for (int j = 0; j < 4; j++) acc[i][j] += qa[i] * ka[j];
        }

        bool diag = (st == qt);
        float p[4][4];
        #pragma unroll
        for (int i = 0; i < 4; i++) {
            int gi = ty * 4 + i;
            float rmax = -INFINITY;
            #pragma unroll
            for (int j = 0; j < 4; j++) {
                float sv = acc[i][j];
                if (diag && (tx * 4 + j) > gi) sv = -INFINITY;
                acc[i][j] = sv;
                rmax = fmaxf(rmax, sv);
            }
            #pragma unroll
            for (int off = 1; off < 16; off <<= 1)
                rmax = fmaxf(rmax, __shfl_xor_sync(0xFFFFFFFFu, rmax, off));
            float mn = fmaxf(m[i], rmax);
            float corr = __expf(m[i] - mn);
            float rs = 0.0f;
            #pragma unroll
            for (int j = 0; j < 4; j++) {
                float pv = __expf(acc[i][j] - mn);
                p[i][j] = pv;
                rs += pv;
            }
            #pragma unroll
            for (int off = 1; off < 16; off <<= 1)
                rs += __shfl_xor_sync(0xFFFFFFFFu, rs, off);
            lsum[i] = lsum[i] * corr + rs;
            #pragma unroll
            for (int j = 0; j < 4; j++) o[i][j] *= corr;
            m[i] = mn;
        }

        // write P transposed: Ps[j][i]
        #pragma unroll
        for (int j = 0; j < 4; j++)
            #pragma unroll
            for (int i = 0; i < 4; i++)
                Ps[tx * 4 + j][ty * 4 + i] = p[i][j];
        __syncthreads();

        // O += P @ V
        #pragma unroll
        for (int j = 0; j < 64; j++) {
            float4 pv = *(const float4*)&Ps[j][ty * 4];
            float4 vv = *(const float4*)&Vs[j][tx * 4];
            float pa[4] = {pv.x, pv.y, pv.z, pv.w};
            float va[4] = {vv.x, vv.y, vv.z, vv.w};
            #pragma unroll
            for (int i = 0; i < 4; i++)
                #pragma unroll
                for (int dd = 0; dd < 4; dd++) o[i][dd] += pa[i] * va[dd];
        }
    }

    // normalize and write out [B,T,C] at head offset
    #pragma unroll
    for (int i = 0; i < 4; i++) {
        float inv = 1.0f / lsum[i];
        int row = q0 + ty * 4 + i;
        float4 r;
        r.x = o[i][0] * inv; r.y = o[i][1] * inv;
        r.z = o[i][2] * inv; r.w = o[i][3] * inv;
        *(float4*)(out + ((size_t)(b * SEQ + row)) * CDIM + hoff + tx * 4) = r;
    }
}

// ---------------- launch ----------------------------------------------------
extern "C" void kernel_launch(void* const* d_in, const int* in_sizes, int n_in,
                              void* d_out, int out_size) {
    const float* x    = (const float*)d_in[0];
    const float* Wq   = (const float*)d_in[1];
    const float* bq   = (const float*)d_in[2];
    const float* Wk   = (const float*)d_in[3];
    const float* bk   = (const float*)d_in[4];
    const float* Wv   = (const float*)d_in[5];
    const float* bv   = (const float*)d_in[6];
    const float* Wp   = (const float*)d_in[7];
    const float* bp   = (const float*)d_in[8];
    const float* W1   = (const float*)d_in[9];
    const float* b1   = (const float*)d_in[10];
    const float* W2   = (const float*)d_in[11];
    const float* b2   = (const float*)d_in[12];
    const float* ln1g = (const float*)d_in[13];
    const float* ln1b = (const float*)d_in[14];
    const float* ln2g = (const float*)d_in[15];
    const float* ln2b = (const float*)d_in[16];

    float *h, *qkv, *attn, *x2, *h2, *f1, *wqkv, *bqkv;
    cudaGetSymbolAddress((void**)&h,    g_h);
    cudaGetSymbolAddress((void**)&qkv,  g_qkv);
    cudaGetSymbolAddress((void**)&attn, g_attn);
    cudaGetSymbolAddress((void**)&x2,   g_x2);
    cudaGetSymbolAddress((void**)&h2,   g_h2);
    cudaGetSymbolAddress((void**)&f1,   g_f1);
    cudaGetSymbolAddress((void**)&wqkv, g_wqkv);
    cudaGetSymbolAddress((void**)&bqkv, g_bqkv);

    const int fattn_smem = 4 * 64 * 68 * (int)sizeof(float);  // 69632
    cudaFuncSetAttribute(fattn_kernel,
                         cudaFuncAttributeMaxDynamicSharedMemorySize, fattn_smem);

    // 1. repack per-head QKV weights
    repack_kernel<<<(CDIM * CDIM + 255) / 256, 256>>>(Wq, Wk, Wv, bq, bk, bv,
                                                      wqkv, bqkv);
    // 2. LN1
    ln_kernel<<<BT, 128>>>(x, ln1g, ln1b, h);
    // 3. fused QKV projection: [16384,384] @ [384,1152]
    {
        dim3 grid(QKVN / 128, BT / 128);
        gemm128_kernel<false, false><<<grid, 256>>>(BT, QKVN, CDIM,
                                                    h, wqkv, bqkv, nullptr, qkv);
    }
    // 4. flash-tiled causal attention
    {
        dim3 grid(SEQ / 64, BATCH * NH);
        fattn_kernel<<<grid, 256, fattn_smem>>>(qkv, attn);
    }
    // 5. output projection + residual
    {
        dim3 grid(CDIM / 128, BT / 128);
        gemm128_kernel<false, true><<<grid, 256>>>(BT, CDIM, CDIM,
                                                   attn, Wp, bp, x, x2);
        // 6. LN2
        ln_kernel<<<BT, 128>>>(x2, ln2g, ln2b, h2);
        // 7. FF1 + ReLU
        gemm128_kernel<true, false><<<grid, 256>>>(BT, CDIM, CDIM,
                                                   h2, W1, b1, nullptr, f1);
        // 8. FF2 + residual -> out
        gemm128_kernel<false, true><<<grid, 256>>>(BT, CDIM, CDIM,
                                                   f1, W2, b2, x2, (float*)d_out);
    }
}

// round 9
// speedup vs baseline: 3.2455x; 1.4558x over previous
#include <cuda_runtime.h>
#include <cuda_bf16.h>
#include <math.h>
#include <stdint.h>

// Problem constants
#define BATCH 64
#define SEQ   256
#define BT    16384      // BATCH*SEQ
#define CDIM  384
#define NH    6
#define HD    64
#define QKVN  1152       // 3*CDIM

// GEMM tiling (HMMA mma.sync path)
#define BM  128
#define BN  128
#define BKC 32
#define LDP 40           // smem row pitch in bf16 elems (80B; conflict-free ldmatrix)
#define KTOT 384         // all GEMMs have K = CDIM
#define CHUNKS_PER_SEG (KTOT / BKC)   // 12
#define TOT_CHUNKS (3 * CHUNKS_PER_SEG)  // 36 (3-term split)

// ---------------- scratch (static device globals; no allocation) ------------
__device__ float          g_qkv [BT * QKVN];      // fp32 QKV output
__device__ float          g_x2  [BT * CDIM];      // post-attention residual
__device__ __nv_bfloat16  g_ahi [BT * CDIM];
__device__ __nv_bfloat16  g_alo [BT * CDIM];
__device__ __nv_bfloat16  g_f1hi[BT * CDIM];
__device__ __nv_bfloat16  g_f1lo[BT * CDIM];
__device__ __nv_bfloat16  g_wqkvhi[QKVN * CDIM];  // [N][K] K-major
__device__ __nv_bfloat16  g_wqkvlo[QKVN * CDIM];
__device__ __nv_bfloat16  g_wphi[CDIM * CDIM];
__device__ __nv_bfloat16  g_wplo[CDIM * CDIM];
__device__ __nv_bfloat16  g_w1hi[CDIM * CDIM];
__device__ __nv_bfloat16  g_w1lo[CDIM * CDIM];
__device__ __nv_bfloat16  g_w2hi[CDIM * CDIM];
__device__ __nv_bfloat16  g_w2lo[CDIM * CDIM];
__device__ float          g_bqkv[QKVN];

// ---------------- helpers ----------------------------------------------------
__device__ __forceinline__ void split1(float v, __nv_bfloat16& h, __nv_bfloat16& l) {
    h = __float2bfloat16(v);
    l = __float2bfloat16(v - __bfloat162float(h));
}

__device__ __forceinline__ void ldsm4(uint32_t& r0, uint32_t& r1,
                                      uint32_t& r2, uint32_t& r3, uint32_t a) {
    asm volatile("ldmatrix.sync.aligned.m8n8.x4.shared.b16 {%0,%1,%2,%3}, [%4];"
                 : "=r"(r0), "=r"(r1), "=r"(r2), "=r"(r3) : "r"(a));
}

__device__ __forceinline__ void mma16816(float* c,
                                         uint32_t a0, uint32_t a1,
                                         uint32_t a2, uint32_t a3,
                                         uint32_t b0, uint32_t b1) {
    asm volatile(
        "mma.sync.aligned.m16n8k16.row.col.f32.bf16.bf16.f32 "
        "{%0,%1,%2,%3}, {%4,%5,%6,%7}, {%8,%9}, {%0,%1,%2,%3};"
        : "+f"(c[0]), "+f"(c[1]), "+f"(c[2]), "+f"(c[3])
        : "r"(a0), "r"(a1), "r"(a2), "r"(a3), "r"(b0), "r"(b1));
}

// ---------------- weight conversion kernels ----------------------------------
// Wq/Wk/Wv [H][C][D] -> Wqkv^T hi/lo [N=1152][K=384] bf16 + packed fp32 bias
__global__ void wsplit_qkv_kernel(const float* __restrict__ Wq,
                                  const float* __restrict__ Wk,
                                  const float* __restrict__ Wv,
                                  const float* __restrict__ bq,
                                  const float* __restrict__ bk,
                                  const float* __restrict__ bv,
                                  __nv_bfloat16* __restrict__ whi,
                                  __nv_bfloat16* __restrict__ wlo,
                                  float* __restrict__ bqkv) {
    int idx = blockIdx.x * blockDim.x + threadIdx.x;
    if (idx < QKVN * CDIM) {
        int n = idx / CDIM;
        int c = idx - n * CDIM;
        int nn = n % CDIM;
        int h = nn / HD;
        int d = nn - h * HD;
        const float* W = (n < CDIM) ? Wq : ((n < 2 * CDIM) ? Wk : Wv);
        float v = W[((size_t)h * CDIM + c) * HD + d];
        __nv_bfloat16 hi, lo;
        split1(v, hi, lo);
        whi[idx] = hi;
        wlo[idx] = lo;
    }
    if (idx < QKVN) {
        int nn = idx % CDIM;
        const float* bb = (idx < CDIM) ? bq : ((idx < 2 * CDIM) ? bk : bv);
        bqkv[idx] = bb[nn];
    }
}

// src [K=384][N=384] fp32 -> dst^T hi/lo [N][K] bf16
__global__ void wsplit_t_kernel(const float* __restrict__ src,
                                __nv_bfloat16* __restrict__ dhi,
                                __nv_bfloat16* __restrict__ dlo) {
    int idx = blockIdx.x * blockDim.x + threadIdx.x;
    if (idx >= CDIM * CDIM) return;
    int n = idx / CDIM;
    int k = idx - n * CDIM;
    float v = src[(size_t)k * CDIM + n];
    __nv_bfloat16 hi, lo;
    split1(v, hi, lo);
    dhi[idx] = hi;
    dlo[idx] = lo;
}

// ---------------- LayerNorm + bf16 split: one block per row of 384 -----------
__global__ __launch_bounds__(128) void ln_split_kernel(
    const float* __restrict__ x, const float* __restrict__ g,
    const float* __restrict__ b,
    __nv_bfloat16* __restrict__ ohi, __nv_bfloat16* __restrict__ olo) {
    __shared__ float red1[4];
    __shared__ float red2[4];
    int row = blockIdx.x;
    int tid = threadIdx.x;
    const float* xr = x + (size_t)row * CDIM;

    float v0 = xr[tid], v1 = xr[tid + 128], v2 = xr[tid + 256];
    float s = v0 + v1 + v2;
    #pragma unroll
    for (int o = 16; o > 0; o >>= 1) s += __shfl_xor_sync(0xFFFFFFFFu, s, o);
    if ((tid & 31) == 0) red1[tid >> 5] = s;
    __syncthreads();
    float mu = (red1[0] + red1[1] + red1[2] + red1[3]) * (1.0f / CDIM);

    float d0 = v0 - mu, d1 = v1 - mu, d2 = v2 - mu;
    float sq = d0 * d0 + d1 * d1 + d2 * d2;
    #pragma unroll
    for (int o = 16; o > 0; o >>= 1) sq += __shfl_xor_sync(0xFFFFFFFFu, sq, o);
    if ((tid & 31) == 0) red2[tid >> 5] = sq;
    __syncthreads();
    float var = (red2[0] + red2[1] + red2[2] + red2[3]) * (1.0f / CDIM);
    float rs = rsqrtf(var + 1e-5f);

    size_t base = (size_t)row * CDIM;
    float y0 = d0 * rs * g[tid]       + b[tid];
    float y1 = d1 * rs * g[tid + 128] + b[tid + 128];
    float y2 = d2 * rs * g[tid + 256] + b[tid + 256];
    __nv_bfloat16 h0, l0, h1, l1, h2, l2;
    split1(y0, h0, l0); split1(y1, h1, l1); split1(y2, h2, l2);
    ohi[base + tid] = h0;        olo[base + tid] = l0;
    ohi[base + tid + 128] = h1;  olo[base + tid + 128] = l1;
    ohi[base + tid + 256] = h2;  olo[base + tid + 256] = l2;
}

// ---------------- HMMA bf16-split GEMM ----------------------------------------
// C[M,N] = A[M,K] @ B^T (B stored [N][K]), A = Ahi+Alo, B = Bhi+Blo,
// computed as Ahi*Bhi + Alo*Bhi + Ahi*Blo via mma.sync m16n8k16, fp32 accum.
// CTA: 128x128, 8 warps of 32x64, BK=32, double-buffered smem.
template <bool RELU, bool RESID, bool SPLIT>
__global__ __launch_bounds__(256, 2) void gemm_mma_kernel(
    int N,
    const __nv_bfloat16* __restrict__ Ahi,
    const __nv_bfloat16* __restrict__ Alo,
    const __nv_bfloat16* __restrict__ Bhi,
    const __nv_bfloat16* __restrict__ Blo,
    const float* __restrict__ bias,
    const float* __restrict__ resid,
    float* __restrict__ outf,
    __nv_bfloat16* __restrict__ ohi,
    __nv_bfloat16* __restrict__ olo) {
    __shared__ __nv_bfloat16 As[2][BM * LDP];
    __shared__ __nv_bfloat16 Bs[2][BM * LDP];

    int tid = threadIdx.x;
    int lane = tid & 31;
    int wid = tid >> 5;
    int bm = blockIdx.y * BM;
    int bn = blockIdx.x * BN;

    // global load mapping: 512 16B-chunks per matrix per chunk; 2 per thread
    int r0 = tid >> 2;            // 0..63
    int c4 = (tid & 3) * 8;       // bf16 element offset 0,8,16,24

    // warp tile origin
    int m0w = (wid >> 1) * 32;
    int n0w = (wid & 1) * 64;

    // ldmatrix element offsets (within one buffer)
    uint32_t As0 = (uint32_t)__cvta_generic_to_shared(&As[0][0]);
    uint32_t Bs0 = (uint32_t)__cvta_generic_to_shared(&Bs[0][0]);
    const uint32_t BUFB = BM * LDP * 2;   // bytes per buffer

    uint32_t a_off = ((m0w + (lane & 15)) * LDP + (lane >> 4) * 8) * 2;
    uint32_t b_off[4];
    #pragma unroll
    for (int nb = 0; nb < 4; nb++)
        b_off[nb] = ((n0w + nb * 16 + ((lane >> 4) & 1) * 8 + (lane & 7)) * LDP
                     + ((lane >> 3) & 1) * 8) * 2;

    float acc[2][8][4];
    #pragma unroll
    for (int mi = 0; mi < 2; mi++)
        #pragma unroll
        for (int ni = 0; ni < 8; ni++)
            #pragma unroll
            for (int q = 0; q < 4; q++) acc[mi][ni][q] = 0.0f;

    uint4 pa0, pa1, pb0, pb1;

    // prefetch chunk 0 (seg 0: Ahi, Bhi; kk = 0)
    pa0 = *(const uint4*)(Ahi + (size_t)(bm + r0) * KTOT + c4);
    pa1 = *(const uint4*)(Ahi + (size_t)(bm + r0 + 64) * KTOT + c4);
    pb0 = *(const uint4*)(Bhi + (size_t)(bn + r0) * KTOT + c4);
    pb1 = *(const uint4*)(Bhi + (size_t)(bn + r0 + 64) * KTOT + c4);
    *(uint4*)&As[0][r0 * LDP + c4]        = pa0;
    *(uint4*)&As[0][(r0 + 64) * LDP + c4] = pa1;
    *(uint4*)&Bs[0][r0 * LDP + c4]        = pb0;
    *(uint4*)&Bs[0][(r0 + 64) * LDP + c4] = pb1;
    __syncthreads();

    int buf = 0;
    #pragma unroll 1
    for (int t = 0; t < TOT_CHUNKS; t++) {
        int nt = t + 1;
        if (nt < TOT_CHUNKS) {
            int seg = nt / CHUNKS_PER_SEG;
            int kk = (nt - seg * CHUNKS_PER_SEG) * BKC;
            const __nv_bfloat16* A = (seg == 1) ? Alo : Ahi;
            const __nv_bfloat16* B = (seg == 2) ? Blo : Bhi;
            pa0 = *(const uint4*)(A + (size_t)(bm + r0) * KTOT + kk + c4);
            pa1 = *(const uint4*)(A + (size_t)(bm + r0 + 64) * KTOT + kk + c4);
            pb0 = *(const uint4*)(B + (size_t)(bn + r0) * KTOT + kk + c4);
            pb1 = *(const uint4*)(B + (size_t)(bn + r0 + 64) * KTOT + kk + c4);
        }

        // compute on buf: 2 k16 steps
        uint32_t abase = As0 + buf * BUFB + a_off;
        #pragma unroll
        for (int ks = 0; ks < 2; ks++) {
            uint32_t kb = ks * 32;   // 16 bf16 = 32 bytes
            uint32_t a[2][4];
            ldsm4(a[0][0], a[0][1], a[0][2], a[0][3], abase + kb);
            ldsm4(a[1][0], a[1][1], a[1][2], a[1][3], abase + 16 * LDP * 2 + kb);
            uint32_t bfr[8][2];
            #pragma unroll
            for (int nb = 0; nb < 4; nb++) {
                uint32_t baddr = Bs0 + buf * BUFB + b_off[nb] + kb;
                ldsm4(bfr[2 * nb][0], bfr[2 * nb][1],
                      bfr[2 * nb + 1][0], bfr[2 * nb + 1][1], baddr);
            }
            #pragma unroll
            for (int mi = 0; mi < 2; mi++)
                #pragma unroll
                for (int ni = 0; ni < 8; ni++)
                    mma16816(acc[mi][ni], a[mi][0], a[mi][1], a[mi][2], a[mi][3],
                             bfr[ni][0], bfr[ni][1]);
        }

        if (nt < TOT_CHUNKS) {
            int nb = buf ^ 1;
            *(uint4*)&As[nb][r0 * LDP + c4]        = pa0;
            *(uint4*)&As[nb][(r0 + 64) * LDP + c4] = pa1;
            *(uint4*)&Bs[nb][r0 * LDP + c4]        = pb0;
            *(uint4*)&Bs[nb][(r0 + 64) * LDP + c4] = pb1;
            __syncthreads();
            buf = nb;
        }
    }

    // epilogue: thread holds rows (m0w + mi*16 + lane/4, +8), cols n0w + ni*8 + (lane&3)*2
    int rbase = bm + m0w + (lane >> 2);
    int cbase = bn + n0w + (lane & 3) * 2;
    #pragma unroll
    for (int mi = 0; mi < 2; mi++) {
        #pragma unroll
        for (int half = 0; half < 2; half++) {
            int row = rbase + mi * 16 + half * 8;
            #pragma unroll
            for (int ni = 0; ni < 8; ni++) {
                int col = cbase + ni * 8;
                float vx = acc[mi][ni][half * 2 + 0];
                float vy = acc[mi][ni][half * 2 + 1];
                float2 bv = *(const float2*)(bias + col);
                vx += bv.x; vy += bv.y;
                if (RESID) {
                    float2 rv = *(const float2*)(resid + (size_t)row * N + col);
                    vx += rv.x; vy += rv.y;
                }
                if (RELU) { vx = fmaxf(vx, 0.f); vy = fmaxf(vy, 0.f); }
                if (SPLIT) {
                    union { __nv_bfloat16 b[2]; uint32_t u; } H, L;
                    split1(vx, H.b[0], L.b[0]);
                    split1(vy, H.b[1], L.b[1]);
                    *(uint32_t*)(ohi + (size_t)row * N + col) = H.u;
                    *(uint32_t*)(olo + (size_t)row * N + col) = L.u;
                } else {
                    float2 o; o.x = vx; o.y = vy;
                    *(float2*)(outf + (size_t)row * N + col) = o;
                }
            }
        }
    }
}

// ---------------- flash-tiled causal attention (fp32, bf16-split output) -----
__global__ __launch_bounds__(256) void fattn_kernel(
    const float* __restrict__ qkv,
    __nv_bfloat16* __restrict__ ohi, __nv_bfloat16* __restrict__ olo) {
    extern __shared__ float smf[];
    float (*Qs)[68] = (float(*)[68])(smf);
    float (*Ks)[68] = (float(*)[68])(smf + 64 * 68);
    float (*Vs)[68] = (float(*)[68])(smf + 2 * 64 * 68);
    float (*Ps)[68] = (float(*)[68])(smf + 3 * 64 * 68);

    int qt = blockIdx.x;
    int bh = blockIdx.y;
    int b = bh / NH;
    int h = bh - b * NH;
    const float* base = qkv + (size_t)b * SEQ * QKVN;
    int hoff = h * HD;
    int q0 = qt * 64;
    int tid = threadIdx.x;
    int tx = tid & 15;
    int ty = tid >> 4;
    const float scale = rsqrtf((float)CDIM);

    #pragma unroll
    for (int l = 0; l < 4; l++) {
        int idx = tid + l * 256;
        int i = idx >> 4, d4 = (idx & 15) * 4;
        float4 v = *(const float4*)(base + (size_t)(q0 + i) * QKVN + hoff + d4);
        Qs[d4 + 0][i] = v.x * scale; Qs[d4 + 1][i] = v.y * scale;
        Qs[d4 + 2][i] = v.z * scale; Qs[d4 + 3][i] = v.w * scale;
    }

    float m[4], lsum[4], o[4][4];
    #pragma unroll
    for (int i = 0; i < 4; i++) {
        m[i] = -INFINITY; lsum[i] = 0.0f;
        #pragma unroll
        for (int j = 0; j < 4; j++) o[i][j] = 0.0f;
    }

    for (int st = 0; st <= qt; st++) {
        int s0 = st * 64;
        __syncthreads();
        #pragma unroll
        for (int l = 0; l < 4; l++) {
            int idx = tid + l * 256;
            int j = idx >> 4, d4 = (idx & 15) * 4;
            const float* rp = base + (size_t)(s0 + j) * QKVN + hoff;
            float4 kv = *(const float4*)(rp + CDIM + d4);
            Ks[d4 + 0][j] = kv.x; Ks[d4 + 1][j] = kv.y;
            Ks[d4 + 2][j] = kv.z; Ks[d4 + 3][j] = kv.w;
            float4 vv = *(const float4*)(rp + 2 * CDIM + d4);
            *(float4*)&Vs[j][d4] = vv;
        }
        __syncthreads();

        float acc[4][4];
        #pragma unroll
        for (int i = 0; i < 4; i++)
            #pragma unroll
            for (int j = 0; j < 4; j++) acc[i][j] = 0.0f;
        #pragma unroll
        for (int d = 0; d < 64; d++) {
            float4 qv = *(const float4*)&Qs[d][ty * 4];
            float4 kv = *(const float4*)&Ks[d][tx * 4];
            float qa[4] = {qv.x, qv.y, qv.z, qv.w};
            float ka[4] = {kv.x, kv.y, kv.z, kv.w};
            #pragma unroll
            for (int i = 0; i < 4; i++)
                #pragma unroll
                for (int j = 0; j < 4; j++) acc[i][j] += qa[i] * ka[j];
        }

        bool diag = (st == qt);
        float p[4][4];
        #pragma unroll
        for (int i = 0; i < 4; i++) {
            int gi = ty * 4 + i;
            float rmax = -INFINITY;
            #pragma unroll
            for (int j = 0; j < 4; j++) {
                float sv = acc[i][j];
                if (diag && (tx * 4 + j) > gi) sv = -INFINITY;
                acc[i][j] = sv;
                rmax = fmaxf(rmax, sv);
            }
            #pragma unroll
            for (int off = 1; off < 16; off <<= 1)
                rmax = fmaxf(rmax, __shfl_xor_sync(0xFFFFFFFFu, rmax, off));
            float mn = fmaxf(m[i], rmax);
            float corr = __expf(m[i] - mn);
            float rs = 0.0f;
            #pragma unroll
            for (int j = 0; j < 4; j++) {
                float pv = __expf(acc[i][j] - mn);
                p[i][j] = pv;
                rs += pv;
            }
            #pragma unroll
            for (int off = 1; off < 16; off <<= 1)
                rs += __shfl_xor_sync(0xFFFFFFFFu, rs, off);
            lsum[i] = lsum[i] * corr + rs;
            #pragma unroll
            for (int j = 0; j < 4; j++) o[i][j] *= corr;
            m[i] = mn;
        }

        #pragma unroll
        for (int j = 0; j < 4; j++)
            #pragma unroll
            for (int i = 0; i < 4; i++)
                Ps[tx * 4 + j][ty * 4 + i] = p[i][j];
        __syncthreads();

        #pragma unroll
        for (int j = 0; j < 64; j++) {
            float4 pv = *(const float4*)&Ps[j][ty * 4];
            float4 vv = *(const float4*)&Vs[j][tx * 4];
            float pa[4] = {pv.x, pv.y, pv.z, pv.w};
            float va[4] = {vv.x, vv.y, vv.z, vv.w};
            #pragma unroll
            for (int i = 0; i < 4; i++)
                #pragma unroll
                for (int dd = 0; dd < 4; dd++) o[i][dd] += pa[i] * va[dd];
        }
    }

    #pragma unroll
    for (int i = 0; i < 4; i++) {
        float inv = 1.0f / lsum[i];
        int row = q0 + ty * 4 + i;
        size_t off = ((size_t)(b * SEQ + row)) * CDIM + hoff + tx * 4;
        union { __nv_bfloat16 b[4]; uint2 u; } H, L;
        split1(o[i][0] * inv, H.b[0], L.b[0]);
        split1(o[i][1] * inv, H.b[1], L.b[1]);
        split1(o[i][2] * inv, H.b[2], L.b[2]);
        split1(o[i][3] * inv, H.b[3], L.b[3]);
        *(uint2*)(ohi + off) = H.u;
        *(uint2*)(olo + off) = L.u;
    }
}

// ---------------- launch ------------------------------------------------------
extern "C" void kernel_launch(void* const* d_in, const int* in_sizes, int n_in,
                              void* d_out, int out_size) {
    const float* x    = (const float*)d_in[0];
    const float* Wq   = (const float*)d_in[1];
    const float* bq   = (const float*)d_in[2];
    const float* Wk   = (const float*)d_in[3];
    const float* bk   = (const float*)d_in[4];
    const float* Wv   = (const float*)d_in[5];
    const float* bv   = (const float*)d_in[6];
    const float* Wp   = (const float*)d_in[7];
    const float* bp   = (const float*)d_in[8];
    const float* W1   = (const float*)d_in[9];
    const float* b1   = (const float*)d_in[10];
    const float* W2   = (const float*)d_in[11];
    const float* b2   = (const float*)d_in[12];
    const float* ln1g = (const float*)d_in[13];
    const float* ln1b = (const float*)d_in[14];
    const float* ln2g = (const float*)d_in[15];
    const float* ln2b = (const float*)d_in[16];

    float *qkv, *x2, *bqkv;
    __nv_bfloat16 *ahi, *alo, *f1hi, *f1lo;
    __nv_bfloat16 *wqh, *wql, *wph, *wpl, *w1h, *w1l, *w2h, *w2l;
    cudaGetSymbolAddress((void**)&qkv,  g_qkv);
    cudaGetSymbolAddress((void**)&x2,   g_x2);
    cudaGetSymbolAddress((void**)&bqkv, g_bqkv);
    cudaGetSymbolAddress((void**)&ahi,  g_ahi);
    cudaGetSymbolAddress((void**)&alo,  g_alo);
    cudaGetSymbolAddress((void**)&f1hi, g_f1hi);
    cudaGetSymbolAddress((void**)&f1lo, g_f1lo);
    cudaGetSymbolAddress((void**)&wqh,  g_wqkvhi);
    cudaGetSymbolAddress((void**)&wql,  g_wqkvlo);
    cudaGetSymbolAddress((void**)&wph,  g_wphi);
    cudaGetSymbolAddress((void**)&wpl,  g_wplo);
    cudaGetSymbolAddress((void**)&w1h,  g_w1hi);
    cudaGetSymbolAddress((void**)&w1l,  g_w1lo);
    cudaGetSymbolAddress((void**)&w2h,  g_w2hi);
    cudaGetSymbolAddress((void**)&w2l,  g_w2lo);

    const int fattn_smem = 4 * 64 * 68 * (int)sizeof(float);
    cudaFuncSetAttribute(fattn_kernel,
                         cudaFuncAttributeMaxDynamicSharedMemorySize, fattn_smem);

    // weight conversions (bf16 hi/lo, transposed to [N][K])
    wsplit_qkv_kernel<<<(QKVN * CDIM + 255) / 256, 256>>>(Wq, Wk, Wv, bq, bk, bv,
                                                          wqh, wql, bqkv);
    wsplit_t_kernel<<<(CDIM * CDIM + 255) / 256, 256>>>(Wp, wph, wpl);
    wsplit_t_kernel<<<(CDIM * CDIM + 255) / 256, 256>>>(W1, w1h, w1l);
    wsplit_t_kernel<<<(CDIM * CDIM + 255) / 256, 256>>>(W2, w2h, w2l);

    // LN1 -> bf16 hi/lo
    ln_split_kernel<<<BT, 128>>>(x, ln1g, ln1b, ahi, alo);

    // QKV projection: [16384,384] x [384,1152] -> fp32
    {
        dim3 grid(QKVN / BN, BT / BM);
        gemm_mma_kernel<false, false, false><<<grid, 256>>>(
            QKVN, ahi, alo, wqh, wql, bqkv, nullptr, qkv, nullptr, nullptr);
    }
    // attention -> bf16 hi/lo (reuses ahi/alo)
    {
        dim3 grid(SEQ / 64, BATCH * NH);
        fattn_kernel<<<grid, 256, fattn_smem>>>(qkv, ahi, alo);
    }
    // output projection + residual(x) -> x2 fp32
    {
        dim3 grid(CDIM / BN, BT / BM);
        gemm_mma_kernel<false, true, false><<<grid, 256>>>(
            CDIM, ahi, alo, wph, wpl, bp, x, x2, nullptr, nullptr);
        // LN2 -> bf16 hi/lo
        ln_split_kernel<<<BT, 128>>>(x2, ln2g, ln2b, ahi, alo);
        // FF1 + ReLU -> bf16 hi/lo
        gemm_mma_kernel<true, false, true><<<grid, 256>>>(
            CDIM, ahi, alo, w1h, w1l, b1, nullptr, nullptr, f1hi, f1lo);
        // FF2 + residual(x2) -> d_out fp32
        gemm_mma_kernel<false, true, false><<<grid, 256>>>(
            CDIM, f1hi, f1lo, w2h, w2l, b2, x2, (float*)d_out, nullptr, nullptr);
    }
}

// round 14
// speedup vs baseline: 3.7824x; 1.1654x over previous
#include <cuda_runtime.h>
#include <cuda_bf16.h>
#include <math.h>
#include <stdint.h>

// Problem constants
#define BATCH 64
#define SEQ   256
#define BT    16384      // BATCH*SEQ
#define CDIM  384
#define NH    6
#define HD    64
#define QKVN  1152       // 3*CDIM

// GEMM tiling (HMMA mma.sync path)
#define BM  128
#define BN  128
#define BKC 32
#define LDP 40           // smem row pitch in bf16 elems
#define KTOT 384
#define CHUNKS_PER_SEG (KTOT / BKC)      // 12
#define TOT_CHUNKS (3 * CHUNKS_PER_SEG)  // 36

// attention smem pitch (bf16 elems); 144B rows -> conflict-free ldmatrix
#define ATP 72

// ---------------- scratch (static device globals; no allocation) ------------
__device__ __nv_bfloat16  g_qkvhi[BT * QKVN];
__device__ __nv_bfloat16  g_qkvlo[BT * QKVN];
__device__ float          g_x2  [BT * CDIM];
__device__ __nv_bfloat16  g_ahi [BT * CDIM];
__device__ __nv_bfloat16  g_alo [BT * CDIM];
__device__ __nv_bfloat16  g_f1hi[BT * CDIM];
__device__ __nv_bfloat16  g_f1lo[BT * CDIM];
__device__ __nv_bfloat16  g_wqkvhi[QKVN * CDIM];  // [N][K] K-major
__device__ __nv_bfloat16  g_wqkvlo[QKVN * CDIM];
__device__ __nv_bfloat16  g_wphi[CDIM * CDIM];
__device__ __nv_bfloat16  g_wplo[CDIM * CDIM];
__device__ __nv_bfloat16  g_w1hi[CDIM * CDIM];
__device__ __nv_bfloat16  g_w1lo[CDIM * CDIM];
__device__ __nv_bfloat16  g_w2hi[CDIM * CDIM];
__device__ __nv_bfloat16  g_w2lo[CDIM * CDIM];
__device__ float          g_bqkv[QKVN];

// ---------------- helpers ----------------------------------------------------
__device__ __forceinline__ void split1(float v, __nv_bfloat16& h, __nv_bfloat16& l) {
    h = __float2bfloat16(v);
    l = __float2bfloat16(v - __bfloat162float(h));
}

__device__ __forceinline__ void ldsm4(uint32_t& r0, uint32_t& r1,
                                      uint32_t& r2, uint32_t& r3, uint32_t a) {
    asm volatile("ldmatrix.sync.aligned.m8n8.x4.shared.b16 {%0,%1,%2,%3}, [%4];"
                 : "=r"(r0), "=r"(r1), "=r"(r2), "=r"(r3) : "r"(a));
}

__device__ __forceinline__ void ldsm4t(uint32_t& r0, uint32_t& r1,
                                       uint32_t& r2, uint32_t& r3, uint32_t a) {
    asm volatile("ldmatrix.sync.aligned.m8n8.x4.trans.shared.b16 {%0,%1,%2,%3}, [%4];"
                 : "=r"(r0), "=r"(r1), "=r"(r2), "=r"(r3) : "r"(a));
}

__device__ __forceinline__ void mma16816(float* c,
                                         uint32_t a0, uint32_t a1,
                                         uint32_t a2, uint32_t a3,
                                         uint32_t b0, uint32_t b1) {
    asm volatile(
        "mma.sync.aligned.m16n8k16.row.col.f32.bf16.bf16.f32 "
        "{%0,%1,%2,%3}, {%4,%5,%6,%7}, {%8,%9}, {%0,%1,%2,%3};"
        : "+f"(c[0]), "+f"(c[1]), "+f"(c[2]), "+f"(c[3])
        : "r"(a0), "r"(a1), "r"(a2), "r"(a3), "r"(b0), "r"(b1));
}

// pack (lo elem, hi elem) into bf16x2
__device__ __forceinline__ uint32_t pack2(float lo, float hi) {
    uint32_t r;
    asm("cvt.rn.bf16x2.f32 %0, %1, %2;" : "=r"(r) : "f"(hi), "f"(lo));
    return r;
}
__device__ __forceinline__ float bf16lo_f(uint32_t u) {
    return __uint_as_float(u << 16);
}
__device__ __forceinline__ float bf16hi_f(uint32_t u) {
    return __uint_as_float(u & 0xFFFF0000u);
}

// ---------------- weight conversion kernels ----------------------------------
__global__ void wsplit_qkv_kernel(const float* __restrict__ Wq,
                                  const float* __restrict__ Wk,
                                  const float* __restrict__ Wv,
                                  const float* __restrict__ bq,
                                  const float* __restrict__ bk,
                                  const float* __restrict__ bv,
                                  __nv_bfloat16* __restrict__ whi,
                                  __nv_bfloat16* __restrict__ wlo,
                                  float* __restrict__ bqkv) {
    int idx = blockIdx.x * blockDim.x + threadIdx.x;
    if (idx < QKVN * CDIM) {
        int n = idx / CDIM;
        int c = idx - n * CDIM;
        int nn = n % CDIM;
        int h = nn / HD;
        int d = nn - h * HD;
        const float* W = (n < CDIM) ? Wq : ((n < 2 * CDIM) ? Wk : Wv);
        float v = W[((size_t)h * CDIM + c) * HD + d];
        __nv_bfloat16 hi, lo;
        split1(v, hi, lo);
        whi[idx] = hi;
        wlo[idx] = lo;
    }
    if (idx < QKVN) {
        int nn = idx % CDIM;
        const float* bb = (idx < CDIM) ? bq : ((idx < 2 * CDIM) ? bk : bv);
        bqkv[idx] = bb[nn];
    }
}

__global__ void wsplit_t_kernel(const float* __restrict__ src,
                                __nv_bfloat16* __restrict__ dhi,
                                __nv_bfloat16* __restrict__ dlo) {
    int idx = blockIdx.x * blockDim.x + threadIdx.x;
    if (idx >= CDIM * CDIM) return;
    int n = idx / CDIM;
    int k = idx - n * CDIM;
    float v = src[(size_t)k * CDIM + n];
    __nv_bfloat16 hi, lo;
    split1(v, hi, lo);
    dhi[idx] = hi;
    dlo[idx] = lo;
}

// ---------------- LayerNorm + bf16 split -------------------------------------
__global__ __launch_bounds__(128) void ln_split_kernel(
    const float* __restrict__ x, const float* __restrict__ g,
    const float* __restrict__ b,
    __nv_bfloat16* __restrict__ ohi, __nv_bfloat16* __restrict__ olo) {
    __shared__ float red1[4];
    __shared__ float red2[4];
    int row = blockIdx.x;
    int tid = threadIdx.x;
    const float* xr = x + (size_t)row * CDIM;

    float v0 = xr[tid], v1 = xr[tid + 128], v2 = xr[tid + 256];
    float s = v0 + v1 + v2;
    #pragma unroll
    for (int o = 16; o > 0; o >>= 1) s += __shfl_xor_sync(0xFFFFFFFFu, s, o);
    if ((tid & 31) == 0) red1[tid >> 5] = s;
    __syncthreads();
    float mu = (red1[0] + red1[1] + red1[2] + red1[3]) * (1.0f / CDIM);

    float d0 = v0 - mu, d1 = v1 - mu, d2 = v2 - mu;
    float sq = d0 * d0 + d1 * d1 + d2 * d2;
    #pragma unroll
    for (int o = 16; o > 0; o >>= 1) sq += __shfl_xor_sync(0xFFFFFFFFu, sq, o);
    if ((tid & 31) == 0) red2[tid >> 5] = sq;
    __syncthreads();
    float var = (red2[0] + red2[1] + red2[2] + red2[3]) * (1.0f / CDIM);
    float rs = rsqrtf(var + 1e-5f);

    size_t base = (size_t)row * CDIM;
    float y0 = d0 * rs * g[tid]       + b[tid];
    float y1 = d1 * rs * g[tid + 128] + b[tid + 128];
    float y2 = d2 * rs * g[tid + 256] + b[tid + 256];
    __nv_bfloat16 h0, l0, h1, l1, h2, l2;
    split1(y0, h0, l0); split1(y1, h1, l1); split1(y2, h2, l2);
    ohi[base + tid] = h0;        olo[base + tid] = l0;
    ohi[base + tid + 128] = h1;  olo[base + tid + 128] = l1;
    ohi[base + tid + 256] = h2;  olo[base + tid + 256] = l2;
}

// ---------------- HMMA bf16-split GEMM ----------------------------------------
template <bool RELU, bool RESID, bool SPLIT>
__global__ __launch_bounds__(256, 2) void gemm_mma_kernel(
    int N,
    const __nv_bfloat16* __restrict__ Ahi,
    const __nv_bfloat16* __restrict__ Alo,
    const __nv_bfloat16* __restrict__ Bhi,
    const __nv_bfloat16* __restrict__ Blo,
    const float* __restrict__ bias,
    const float* __restrict__ resid,
    float* __restrict__ outf,
    __nv_bfloat16* __restrict__ ohi,
    __nv_bfloat16* __restrict__ olo) {
    __shared__ __nv_bfloat16 As[2][BM * LDP];
    __shared__ __nv_bfloat16 Bs[2][BM * LDP];

    int tid = threadIdx.x;
    int lane = tid & 31;
    int wid = tid >> 5;
    int bm = blockIdx.y * BM;
    int bn = blockIdx.x * BN;

    int r0 = tid >> 2;
    int c4 = (tid & 3) * 8;

    int m0w = (wid >> 1) * 32;
    int n0w = (wid & 1) * 64;

    uint32_t As0 = (uint32_t)__cvta_generic_to_shared(&As[0][0]);
    uint32_t Bs0 = (uint32_t)__cvta_generic_to_shared(&Bs[0][0]);
    const uint32_t BUFB = BM * LDP * 2;

    uint32_t a_off = ((m0w + (lane & 15)) * LDP + (lane >> 4) * 8) * 2;
    uint32_t b_off[4];
    #pragma unroll
    for (int nb = 0; nb < 4; nb++)
        b_off[nb] = ((n0w + nb * 16 + ((lane >> 4) & 1) * 8 + (lane & 7)) * LDP
                     + ((lane >> 3) & 1) * 8) * 2;

    float acc[2][8][4];
    #pragma unroll
    for (int mi = 0; mi < 2; mi++)
        #pragma unroll
        for (int ni = 0; ni < 8; ni++)
            #pragma unroll
            for (int q = 0; q < 4; q++) acc[mi][ni][q] = 0.0f;

    uint4 pa0, pa1, pb0, pb1;

    pa0 = *(const uint4*)(Ahi + (size_t)(bm + r0) * KTOT + c4);
    pa1 = *(const uint4*)(Ahi + (size_t)(bm + r0 + 64) * KTOT + c4);
    pb0 = *(const uint4*)(Bhi + (size_t)(bn + r0) * KTOT + c4);
    pb1 = *(const uint4*)(Bhi + (size_t)(bn + r0 + 64) * KTOT + c4);
    *(uint4*)&As[0][r0 * LDP + c4]        = pa0;
    *(uint4*)&As[0][(r0 + 64) * LDP + c4] = pa1;
    *(uint4*)&Bs[0][r0 * LDP + c4]        = pb0;
    *(uint4*)&Bs[0][(r0 + 64) * LDP + c4] = pb1;
    __syncthreads();

    int buf = 0;
    #pragma unroll 1
    for (int t = 0; t < TOT_CHUNKS; t++) {
        int nt = t + 1;
        if (nt < TOT_CHUNKS) {
            int seg = nt / CHUNKS_PER_SEG;
            int kk = (nt - seg * CHUNKS_PER_SEG) * BKC;
            const __nv_bfloat16* A = (seg == 1) ? Alo : Ahi;
            const __nv_bfloat16* B = (seg == 2) ? Blo : Bhi;
            pa0 = *(const uint4*)(A + (size_t)(bm + r0) * KTOT + kk + c4);
            pa1 = *(const uint4*)(A + (size_t)(bm + r0 + 64) * KTOT + kk + c4);
            pb0 = *(const uint4*)(B + (size_t)(bn + r0) * KTOT + kk + c4);
            pb1 = *(const uint4*)(B + (size_t)(bn + r0 + 64) * KTOT + kk + c4);
        }

        uint32_t abase = As0 + buf * BUFB + a_off;
        #pragma unroll
        for (int ks = 0; ks < 2; ks++) {
            uint32_t kb = ks * 32;
            uint32_t a[2][4];
            ldsm4(a[0][0], a[0][1], a[0][2], a[0][3], abase + kb);
            ldsm4(a[1][0], a[1][1], a[1][2], a[1][3], abase + 16 * LDP * 2 + kb);
            uint32_t bfr[8][2];
            #pragma unroll
            for (int nb = 0; nb < 4; nb++) {
                uint32_t baddr = Bs0 + buf * BUFB + b_off[nb] + kb;
                ldsm4(bfr[2 * nb][0], bfr[2 * nb][1],
                      bfr[2 * nb + 1][0], bfr[2 * nb + 1][1], baddr);
            }
            #pragma unroll
            for (int mi = 0; mi < 2; mi++)
                #pragma unroll
                for (int ni = 0; ni < 8; ni++)
                    mma16816(acc[mi][ni], a[mi][0], a[mi][1], a[mi][2], a[mi][3],
                             bfr[ni][0], bfr[ni][1]);
        }

        if (nt < TOT_CHUNKS) {
            int nb = buf ^ 1;
            *(uint4*)&As[nb][r0 * LDP + c4]        = pa0;
            *(uint4*)&As[nb][(r0 + 64) * LDP + c4] = pa1;
            *(uint4*)&Bs[nb][r0 * LDP + c4]        = pb0;
            *(uint4*)&Bs[nb][(r0 + 64) * LDP + c4] = pb1;
            __syncthreads();
            buf = nb;
        }
    }

    int rbase = bm + m0w + (lane >> 2);
    int cbase = bn + n0w + (lane & 3) * 2;
    #pragma unroll
    for (int mi = 0; mi < 2; mi++) {
        #pragma unroll
        for (int half = 0; half < 2; half++) {
            int row = rbase + mi * 16 + half * 8;
            #pragma unroll
            for (int ni = 0; ni < 8; ni++) {
                int col = cbase + ni * 8;
                float vx = acc[mi][ni][half * 2 + 0];
                float vy = acc[mi][ni][half * 2 + 1];
                float2 bv = *(const float2*)(bias + col);
                vx += bv.x; vy += bv.y;
                if (RESID) {
                    float2 rv = *(const float2*)(resid + (size_t)row * N + col);
                    vx += rv.x; vy += rv.y;
                }
                if (RELU) { vx = fmaxf(vx, 0.f); vy = fmaxf(vy, 0.f); }
                if (SPLIT) {
                    union { __nv_bfloat16 b[2]; uint32_t u; } H, L;
                    split1(vx, H.b[0], L.b[0]);
                    split1(vy, H.b[1], L.b[1]);
                    *(uint32_t*)(ohi + (size_t)row * N + col) = H.u;
                    *(uint32_t*)(olo + (size_t)row * N + col) = L.u;
                } else {
                    float2 o; o.x = vx; o.y = vy;
                    *(float2*)(outf + (size_t)row * N + col) = o;
                }
            }
        }
    }
}

// ---------------- HMMA flash attention ----------------------------------------
// grid (4, B*H), 128 threads (4 warps). Warp w: query rows q0+16w..q0+16w+15.
// QKV in bf16 hi/lo planar [t][1152]. 3-term split on both QK^T and PV.
__global__ __launch_bounds__(128) void fattn_mma_kernel(
    const __nv_bfloat16* __restrict__ qh, const __nv_bfloat16* __restrict__ ql,
    __nv_bfloat16* __restrict__ ohi, __nv_bfloat16* __restrict__ olo) {
    extern __shared__ __nv_bfloat16 smb[];
    __nv_bfloat16* Qh = smb;
    __nv_bfloat16* Ql = smb + 64 * ATP;
    __nv_bfloat16* Kh = smb + 2 * 64 * ATP;
    __nv_bfloat16* Kl = smb + 3 * 64 * ATP;
    __nv_bfloat16* Vh = smb + 4 * 64 * ATP;
    __nv_bfloat16* Vl = smb + 5 * 64 * ATP;

    int qt = blockIdx.x;
    int bh = blockIdx.y;
    int b = bh / NH;
    int h = bh - b * NH;
    int hoff = h * HD;
    int q0 = qt * 64;
    int tid = threadIdx.x;
    int lane = tid & 31;
    int w = tid >> 5;
    size_t tokbase = (size_t)b * SEQ;

    // load Q hi/lo tiles
    #pragma unroll
    for (int i = 0; i < 4; i++) {
        int idx = tid + i * 128;
        int r = idx >> 3, c8 = (idx & 7) * 8;
        size_t off = (tokbase + q0 + r) * QKVN + hoff + c8;
        *(uint4*)&Qh[r * ATP + c8] = *(const uint4*)(qh + off);
        *(uint4*)&Ql[r * ATP + c8] = *(const uint4*)(ql + off);
    }

    uint32_t sQh = (uint32_t)__cvta_generic_to_shared(Qh);
    uint32_t sQl = (uint32_t)__cvta_generic_to_shared(Ql);
    uint32_t sKh = (uint32_t)__cvta_generic_to_shared(Kh);
    uint32_t sKl = (uint32_t)__cvta_generic_to_shared(Kl);
    uint32_t sVh = (uint32_t)__cvta_generic_to_shared(Vh);
    uint32_t sVl = (uint32_t)__cvta_generic_to_shared(Vl);

    // fragment byte offsets
    uint32_t a_byte = ((w * 16 + (lane & 15)) * ATP + (lane >> 4) * 8) * 2;
    uint32_t kb_byte[4];
    #pragma unroll
    for (int nb = 0; nb < 4; nb++)
        kb_byte[nb] = ((nb * 16 + ((lane >> 4) & 1) * 8 + (lane & 7)) * ATP
                       + ((lane >> 3) & 1) * 8) * 2;
    uint32_t v_row = ((lane >> 3) & 1) * 8 + (lane & 7);
    uint32_t v_col = ((lane >> 4) & 1) * 8;

    float m0 = -INFINITY, m1 = -INFINITY, l0 = 0.f, l1 = 0.f;
    float oacc[8][4];
    #pragma unroll
    for (int i = 0; i < 8; i++)
        #pragma unroll
        for (int q = 0; q < 4; q++) oacc[i][q] = 0.f;

    const float scale = rsqrtf((float)CDIM);

    #pragma unroll 1
    for (int st = 0; st <= qt; st++) {
        int s0 = st * 64;
        __syncthreads();
        #pragma unroll
        for (int i = 0; i < 4; i++) {
            int idx = tid + i * 128;
            int r = idx >> 3, c8 = (idx & 7) * 8;
            size_t off = (tokbase + s0 + r) * QKVN + hoff + c8;
            *(uint4*)&Kh[r * ATP + c8] = *(const uint4*)(qh + off + CDIM);
            *(uint4*)&Kl[r * ATP + c8] = *(const uint4*)(ql + off + CDIM);
            *(uint4*)&Vh[r * ATP + c8] = *(const uint4*)(qh + off + 2 * CDIM);
            *(uint4*)&Vl[r * ATP + c8] = *(const uint4*)(ql + off + 2 * CDIM);
        }
        __syncthreads();

        // ---- S = Q K^T (3-term split) ----
        float sacc[8][4];
        #pragma unroll
        for (int i = 0; i < 8; i++)
            #pragma unroll
            for (int q = 0; q < 4; q++) sacc[i][q] = 0.f;

        #pragma unroll
        for (int ks = 0; ks < 4; ks++) {
            uint32_t kb = ks * 32;
            uint32_t ah[4], al[4];
            ldsm4(ah[0], ah[1], ah[2], ah[3], sQh + a_byte + kb);
            ldsm4(al[0], al[1], al[2], al[3], sQl + a_byte + kb);
            #pragma unroll
            for (int nb = 0; nb < 4; nb++) {
                uint32_t kh[4], kl[4];
                ldsm4(kh[0], kh[1], kh[2], kh[3], sKh + kb_byte[nb] + kb);
                ldsm4(kl[0], kl[1], kl[2], kl[3], sKl + kb_byte[nb] + kb);
                mma16816(sacc[2 * nb],     ah[0], ah[1], ah[2], ah[3], kh[0], kh[1]);
                mma16816(sacc[2 * nb + 1], ah[0], ah[1], ah[2], ah[3], kh[2], kh[3]);
                mma16816(sacc[2 * nb],     al[0], al[1], al[2], al[3], kh[0], kh[1]);
                mma16816(sacc[2 * nb + 1], al[0], al[1], al[2], al[3], kh[2], kh[3]);
                mma16816(sacc[2 * nb],     ah[0], ah[1], ah[2], ah[3], kl[0], kl[1]);
                mma16816(sacc[2 * nb + 1], ah[0], ah[1], ah[2], ah[3], kl[2], kl[3]);
            }
        }

        // ---- softmax (online) ----
        #pragma unroll
        for (int nf = 0; nf < 8; nf++)
            #pragma unroll
            for (int q = 0; q < 4; q++) sacc[nf][q] *= scale;

        if (st == qt) {
            int lr0 = w * 16 + (lane >> 2);
            #pragma unroll
            for (int nf = 0; nf < 8; nf++) {
                #pragma unroll
                for (int q = 0; q < 4; q++) {
                    int col = nf * 8 + (lane & 3) * 2 + (q & 1);
                    int row = lr0 + ((q >> 1) << 3);
                    if (col > row) sacc[nf][q] = -INFINITY;
                }
            }
        }

        float mx0 = -INFINITY, mx1 = -INFINITY;
        #pragma unroll
        for (int nf = 0; nf < 8; nf++) {
            mx0 = fmaxf(mx0, fmaxf(sacc[nf][0], sacc[nf][1]));
            mx1 = fmaxf(mx1, fmaxf(sacc[nf][2], sacc[nf][3]));
        }
        mx0 = fmaxf(mx0, __shfl_xor_sync(0xFFFFFFFFu, mx0, 1));
        mx0 = fmaxf(mx0, __shfl_xor_sync(0xFFFFFFFFu, mx0, 2));
        mx1 = fmaxf(mx1, __shfl_xor_sync(0xFFFFFFFFu, mx1, 1));
        mx1 = fmaxf(mx1, __shfl_xor_sync(0xFFFFFFFFu, mx1, 2));

        float mn0 = fmaxf(m0, mx0), mn1 = fmaxf(m1, mx1);
        float c0 = __expf(m0 - mn0), c1 = __expf(m1 - mn1);
        m0 = mn0; m1 = mn1;

        float rs0 = 0.f, rs1 = 0.f;
        #pragma unroll
        for (int nf = 0; nf < 8; nf++) {
            sacc[nf][0] = __expf(sacc[nf][0] - mn0); rs0 += sacc[nf][0];
            sacc[nf][1] = __expf(sacc[nf][1] - mn0); rs0 += sacc[nf][1];
            sacc[nf][2] = __expf(sacc[nf][2] - mn1); rs1 += sacc[nf][2];
            sacc[nf][3] = __expf(sacc[nf][3] - mn1); rs1 += sacc[nf][3];
        }
        rs0 += __shfl_xor_sync(0xFFFFFFFFu, rs0, 1);
        rs0 += __shfl_xor_sync(0xFFFFFFFFu, rs0, 2);
        rs1 += __shfl_xor_sync(0xFFFFFFFFu, rs1, 1);
        rs1 += __shfl_xor_sync(0xFFFFFFFFu, rs1, 2);
        l0 = l0 * c0 + rs0;
        l1 = l1 * c1 + rs1;

        #pragma unroll
        for (int nf = 0; nf < 8; nf++) {
            oacc[nf][0] *= c0; oacc[nf][1] *= c0;
            oacc[nf][2] *= c1; oacc[nf][3] *= c1;
        }

        // ---- O += P V (3-term split, P converted in-register) ----
        #pragma unroll
        for (int ks = 0; ks < 4; ks++) {
            uint32_t ph[4], pl[4];
            #pragma unroll
            for (int half = 0; half < 2; half++) {
                int f = 2 * ks + half;
                uint32_t h0 = pack2(sacc[f][0], sacc[f][1]);
                uint32_t h1 = pack2(sacc[f][2], sacc[f][3]);
                ph[2 * half + 0] = h0;
                ph[2 * half + 1] = h1;
                pl[2 * half + 0] = pack2(sacc[f][0] - bf16lo_f(h0),
                                         sacc[f][1] - bf16hi_f(h0));
                pl[2 * half + 1] = pack2(sacc[f][2] - bf16lo_f(h1),
                                         sacc[f][3] - bf16hi_f(h1));
            }
            // reorder: A frag = {a0=(r, k-lo), a1=(r+8, k-lo), a2=(r, k-hi), a3=(r+8, k-hi)}
            // built above as [f=2ks: a0,a1][f=2ks+1: a2,a3] -> already correct order.
            #pragma unroll
            for (int nb2 = 0; nb2 < 4; nb2++) {
                uint32_t voff = ((ks * 16 + v_row) * ATP + nb2 * 16 + v_col) * 2;
                uint32_t vh[4], vl[4];
                ldsm4t(vh[0], vh[1], vh[2], vh[3], sVh + voff);
                ldsm4t(vl[0], vl[1], vl[2], vl[3], sVl + voff);
                mma16816(oacc[2 * nb2],     ph[0], ph[1], ph[2], ph[3], vh[0], vh[1]);
                mma16816(oacc[2 * nb2 + 1], ph[0], ph[1], ph[2], ph[3], vh[2], vh[3]);
                mma16816(oacc[2 * nb2],     pl[0], pl[1], pl[2], pl[3], vh[0], vh[1]);
                mma16816(oacc[2 * nb2 + 1], pl[0], pl[1], pl[2], pl[3], vh[2], vh[3]);
                mma16816(oacc[2 * nb2],     ph[0], ph[1], ph[2], ph[3], vl[0], vl[1]);
                mma16816(oacc[2 * nb2 + 1], ph[0], ph[1], ph[2], ph[3], vl[2], vl[3]);
            }
        }
    }

    // ---- epilogue: normalize, split to bf16 hi/lo, write [B,T,C] ----
    float i0 = 1.0f / l0, i1 = 1.0f / l1;
    int row0 = q0 + w * 16 + (lane >> 2);
    #pragma unroll
    for (int nf = 0; nf < 8; nf++) {
        int col = hoff + nf * 8 + (lane & 3) * 2;
        size_t o0 = (tokbase + row0) * CDIM + col;
        size_t o1 = (tokbase + row0 + 8) * CDIM + col;
        union { __nv_bfloat16 b[2]; uint32_t u; } H, L;
        split1(oacc[nf][0] * i0, H.b[0], L.b[0]);
        split1(oacc[nf][1] * i0, H.b[1], L.b[1]);
        *(uint32_t*)(ohi + o0) = H.u;
        *(uint32_t*)(olo + o0) = L.u;
        split1(oacc[nf][2] * i1, H.b[0], L.b[0]);
        split1(oacc[nf][3] * i1, H.b[1], L.b[1]);
        *(uint32_t*)(ohi + o1) = H.u;
        *(uint32_t*)(olo + o1) = L.u;
    }
}

// ---------------- launch ------------------------------------------------------
extern "C" void kernel_launch(void* const* d_in, const int* in_sizes, int n_in,
                              void* d_out, int out_size) {
    const float* x    = (const float*)d_in[0];
    const float* Wq   = (const float*)d_in[1];
    const float* bq   = (const float*)d_in[2];
    const float* Wk   = (const float*)d_in[3];
    const float* bk   = (const float*)d_in[4];
    const float* Wv   = (const float*)d_in[5];
    const float* bv   = (const float*)d_in[6];
    const float* Wp   = (const float*)d_in[7];
    const float* bp   = (const float*)d_in[8];
    const float* W1   = (const float*)d_in[9];
    const float* b1   = (const float*)d_in[10];
    const float* W2   = (const float*)d_in[11];
    const float* b2   = (const float*)d_in[12];
    const float* ln1g = (const float*)d_in[13];
    const float* ln1b = (const float*)d_in[14];
    const float* ln2g = (const float*)d_in[15];
    const float* ln2b = (const float*)d_in[16];

    float *x2, *bqkv;
    __nv_bfloat16 *qkvh, *qkvl, *ahi, *alo, *f1hi, *f1lo;
    __nv_bfloat16 *wqh, *wql, *wph, *wpl, *w1h, *w1l, *w2h, *w2l;
    cudaGetSymbolAddress((void**)&qkvh, g_qkvhi);
    cudaGetSymbolAddress((void**)&qkvl, g_qkvlo);
    cudaGetSymbolAddress((void**)&x2,   g_x2);
    cudaGetSymbolAddress((void**)&bqkv, g_bqkv);
    cudaGetSymbolAddress((void**)&ahi,  g_ahi);
    cudaGetSymbolAddress((void**)&alo,  g_alo);
    cudaGetSymbolAddress((void**)&f1hi, g_f1hi);
    cudaGetSymbolAddress((void**)&f1lo, g_f1lo);
    cudaGetSymbolAddress((void**)&wqh,  g_wqkvhi);
    cudaGetSymbolAddress((void**)&wql,  g_wqkvlo);
    cudaGetSymbolAddress((void**)&wph,  g_wphi);
    cudaGetSymbolAddress((void**)&wpl,  g_wplo);
    cudaGetSymbolAddress((void**)&w1h,  g_w1hi);
    cudaGetSymbolAddress((void**)&w1l,  g_w1lo);
    cudaGetSymbolAddress((void**)&w2h,  g_w2hi);
    cudaGetSymbolAddress((void**)&w2l,  g_w2lo);

    const int attn_smem = 6 * 64 * ATP * (int)sizeof(__nv_bfloat16);  // 55296
    cudaFuncSetAttribute(fattn_mma_kernel,
                         cudaFuncAttributeMaxDynamicSharedMemorySize, attn_smem);

    // weight conversions
    wsplit_qkv_kernel<<<(QKVN * CDIM + 255) / 256, 256>>>(Wq, Wk, Wv, bq, bk, bv,
                                                          wqh, wql, bqkv);
    wsplit_t_kernel<<<(CDIM * CDIM + 255) / 256, 256>>>(Wp, wph, wpl);
    wsplit_t_kernel<<<(CDIM * CDIM + 255) / 256, 256>>>(W1, w1h, w1l);
    wsplit_t_kernel<<<(CDIM * CDIM + 255) / 256, 256>>>(W2, w2h, w2l);

    // LN1 -> bf16 hi/lo
    ln_split_kernel<<<BT, 128>>>(x, ln1g, ln1b, ahi, alo);

    // QKV projection -> bf16 hi/lo
    {
        dim3 grid(QKVN / BN, BT / BM);
        gemm_mma_kernel<false, false, true><<<grid, 256>>>(
            QKVN, ahi, alo, wqh, wql, bqkv, nullptr, nullptr, qkvh, qkvl);
    }
    // HMMA flash attention -> bf16 hi/lo (reuses ahi/alo)
    {
        dim3 grid(SEQ / 64, BATCH * NH);
        fattn_mma_kernel<<<grid, 128, attn_smem>>>(qkvh, qkvl, ahi, alo);
    }
    // output projection + residual(x) -> x2 fp32
    {
        dim3 grid(CDIM / BN, BT / BM);
        gemm_mma_kernel<false, true, false><<<grid, 256>>>(
            CDIM, ahi, alo, wph, wpl, bp, x, x2, nullptr, nullptr);
        // LN2 -> bf16 hi/lo
        ln_split_kernel<<<BT, 128>>>(x2, ln2g, ln2b, ahi, alo);
        // FF1 + ReLU -> bf16 hi/lo
        gemm_mma_kernel<true, false, true><<<grid, 256>>>(
            CDIM, ahi, alo, w1h, w1l, b1, nullptr, nullptr, f1hi, f1lo);
        // FF2 + residual(x2) -> d_out fp32
        gemm_mma_kernel<false, true, false><<<grid, 256>>>(
            CDIM, f1hi, f1lo, w2h, w2l, b2, x2, (float*)d_out, nullptr, nullptr);
    }
}

// round 15
// speedup vs baseline: 4.4261x; 1.1702x over previous
#include <cuda_runtime.h>
#include <cuda_bf16.h>
#include <math.h>
#include <stdint.h>

// Problem constants
#define BATCH 64
#define SEQ   256
#define BT    16384      // BATCH*SEQ
#define CDIM  384
#define NH    6
#define HD    64
#define QKVN  1152       // 3*CDIM

// GEMM tiling (HMMA mma.sync path)
#define BM  128
#define BN  128
#define BKC 32
#define LDP 40           // smem row pitch in bf16 elems
#define KTOT 384
#define NCHUNK (KTOT / BKC)   // 12

#define TILE_B (BM * LDP * 2)     // bytes per tile (10240)
#define BUFB   (4 * TILE_B)       // bytes per buffer (Ahi,Alo,Bhi,Blo)
#define GSMEM  (2 * BUFB)         // 81920 bytes dynamic smem

// attention smem pitch (bf16 elems)
#define ATP 72

// ---------------- scratch (static device globals; no allocation) ------------
__device__ __nv_bfloat16  g_qkvhi[BT * QKVN];
__device__ __nv_bfloat16  g_qkvlo[BT * QKVN];
__device__ float          g_x2  [BT * CDIM];
__device__ __nv_bfloat16  g_ahi [BT * CDIM];
__device__ __nv_bfloat16  g_alo [BT * CDIM];
__device__ __nv_bfloat16  g_f1hi[BT * CDIM];
__device__ __nv_bfloat16  g_f1lo[BT * CDIM];
__device__ __nv_bfloat16  g_wqkvhi[QKVN * CDIM];  // [N][K] K-major
__device__ __nv_bfloat16  g_wqkvlo[QKVN * CDIM];
__device__ __nv_bfloat16  g_wphi[CDIM * CDIM];
__device__ __nv_bfloat16  g_wplo[CDIM * CDIM];
__device__ __nv_bfloat16  g_w1hi[CDIM * CDIM];
__device__ __nv_bfloat16  g_w1lo[CDIM * CDIM];
__device__ __nv_bfloat16  g_w2hi[CDIM * CDIM];
__device__ __nv_bfloat16  g_w2lo[CDIM * CDIM];
__device__ float          g_bqkv[QKVN];

// ---------------- helpers ----------------------------------------------------
__device__ __forceinline__ void split1(float v, __nv_bfloat16& h, __nv_bfloat16& l) {
    h = __float2bfloat16(v);
    l = __float2bfloat16(v - __bfloat162float(h));
}

__device__ __forceinline__ void ldsm4(uint32_t& r0, uint32_t& r1,
                                      uint32_t& r2, uint32_t& r3, uint32_t a) {
    asm volatile("ldmatrix.sync.aligned.m8n8.x4.shared.b16 {%0,%1,%2,%3}, [%4];"
                 : "=r"(r0), "=r"(r1), "=r"(r2), "=r"(r3) : "r"(a));
}

__device__ __forceinline__ void ldsm4t(uint32_t& r0, uint32_t& r1,
                                       uint32_t& r2, uint32_t& r3, uint32_t a) {
    asm volatile("ldmatrix.sync.aligned.m8n8.x4.trans.shared.b16 {%0,%1,%2,%3}, [%4];"
                 : "=r"(r0), "=r"(r1), "=r"(r2), "=r"(r3) : "r"(a));
}

__device__ __forceinline__ void mma16816(float* c,
                                         uint32_t a0, uint32_t a1,
                                         uint32_t a2, uint32_t a3,
                                         uint32_t b0, uint32_t b1) {
    asm volatile(
        "mma.sync.aligned.m16n8k16.row.col.f32.bf16.bf16.f32 "
        "{%0,%1,%2,%3}, {%4,%5,%6,%7}, {%8,%9}, {%0,%1,%2,%3};"
        : "+f"(c[0]), "+f"(c[1]), "+f"(c[2]), "+f"(c[3])
        : "r"(a0), "r"(a1), "r"(a2), "r"(a3), "r"(b0), "r"(b1));
}

__device__ __forceinline__ void cp16(uint32_t dst, const void* src) {
    asm volatile("cp.async.cg.shared.global [%0], [%1], 16;"
                 :: "r"(dst), "l"(src));
}
#define CP_COMMIT() asm volatile("cp.async.commit_group;" ::: "memory")
#define CP_WAIT(n)  asm volatile("cp.async.wait_group %0;" :: "n"(n) : "memory")

__device__ __forceinline__ uint32_t pack2(float lo, float hi) {
    uint32_t r;
    asm("cvt.rn.bf16x2.f32 %0, %1, %2;" : "=r"(r) : "f"(hi), "f"(lo));
    return r;
}
__device__ __forceinline__ float bf16lo_f(uint32_t u) {
    return __uint_as_float(u << 16);
}
__device__ __forceinline__ float bf16hi_f(uint32_t u) {
    return __uint_as_float(u & 0xFFFF0000u);
}

// ---------------- weight conversion kernels ----------------------------------
__global__ void wsplit_qkv_kernel(const float* __restrict__ Wq,
                                  const float* __restrict__ Wk,
                                  const float* __restrict__ Wv,
                                  const float* __restrict__ bq,
                                  const float* __restrict__ bk,
                                  const float* __restrict__ bv,
                                  __nv_bfloat16* __restrict__ whi,
                                  __nv_bfloat16* __restrict__ wlo,
                                  float* __restrict__ bqkv) {
    int idx = blockIdx.x * blockDim.x + threadIdx.x;
    if (idx < QKVN * CDIM) {
        int n = idx / CDIM;
        int c = idx - n * CDIM;
        int nn = n % CDIM;
        int h = nn / HD;
        int d = nn - h * HD;
        const float* W = (n < CDIM) ? Wq : ((n < 2 * CDIM) ? Wk : Wv);
        float v = W[((size_t)h * CDIM + c) * HD + d];
        __nv_bfloat16 hi, lo;
        split1(v, hi, lo);
        whi[idx] = hi;
        wlo[idx] = lo;
    }
    if (idx < QKVN) {
        int nn = idx % CDIM;
        const float* bb = (idx < CDIM) ? bq : ((idx < 2 * CDIM) ? bk : bv);
        bqkv[idx] = bb[nn];
    }
}

// 3 weight matrices in one launch: blockIdx.y selects Wp/W1/W2
__global__ void wsplit_t3_kernel(const float* __restrict__ Wp,
                                 const float* __restrict__ W1,
                                 const float* __restrict__ W2,
                                 __nv_bfloat16* __restrict__ ph,
                                 __nv_bfloat16* __restrict__ pl,
                                 __nv_bfloat16* __restrict__ h1,
                                 __nv_bfloat16* __restrict__ l1,
                                 __nv_bfloat16* __restrict__ h2,
                                 __nv_bfloat16* __restrict__ l2) {
    int idx = blockIdx.x * blockDim.x + threadIdx.x;
    if (idx >= CDIM * CDIM) return;
    const float* src = (blockIdx.y == 0) ? Wp : ((blockIdx.y == 1) ? W1 : W2);
    __nv_bfloat16* dh = (blockIdx.y == 0) ? ph : ((blockIdx.y == 1) ? h1 : h2);
    __nv_bfloat16* dl = (blockIdx.y == 0) ? pl : ((blockIdx.y == 1) ? l1 : l2);
    int n = idx / CDIM;
    int k = idx - n * CDIM;
    float v = src[(size_t)k * CDIM + n];
    __nv_bfloat16 hi, lo;
    split1(v, hi, lo);
    dh[idx] = hi;
    dl[idx] = lo;
}

// ---------------- LayerNorm + bf16 split -------------------------------------
__global__ __launch_bounds__(128) void ln_split_kernel(
    const float* __restrict__ x, const float* __restrict__ g,
    const float* __restrict__ b,
    __nv_bfloat16* __restrict__ ohi, __nv_bfloat16* __restrict__ olo) {
    __shared__ float red1[4];
    __shared__ float red2[4];
    int row = blockIdx.x;
    int tid = threadIdx.x;
    const float* xr = x + (size_t)row * CDIM;

    float v0 = xr[tid], v1 = xr[tid + 128], v2 = xr[tid + 256];
    float s = v0 + v1 + v2;
    #pragma unroll
    for (int o = 16; o > 0; o >>= 1) s += __shfl_xor_sync(0xFFFFFFFFu, s, o);
    if ((tid & 31) == 0) red1[tid >> 5] = s;
    __syncthreads();
    float mu = (red1[0] + red1[1] + red1[2] + red1[3]) * (1.0f / CDIM);

    float d0 = v0 - mu, d1 = v1 - mu, d2 = v2 - mu;
    float sq = d0 * d0 + d1 * d1 + d2 * d2;
    #pragma unroll
    for (int o = 16; o > 0; o >>= 1) sq += __shfl_xor_sync(0xFFFFFFFFu, sq, o);
    if ((tid & 31) == 0) red2[tid >> 5] = sq;
    __syncthreads();
    float var = (red2[0] + red2[1] + red2[2] + red2[3]) * (1.0f / CDIM);
    float rs = rsqrtf(var + 1e-5f);

    size_t base = (size_t)row * CDIM;
    float y0 = d0 * rs * g[tid]       + b[tid];
    float y1 = d1 * rs * g[tid + 128] + b[tid + 128];
    float y2 = d2 * rs * g[tid + 256] + b[tid + 256];
    __nv_bfloat16 h0, l0, h1, l1, h2, l2;
    split1(y0, h0, l0); split1(y1, h1, l1); split1(y2, h2, l2);
    ohi[base + tid] = h0;        olo[base + tid] = l0;
    ohi[base + tid + 128] = h1;  olo[base + tid + 128] = l1;
    ohi[base + tid + 256] = h2;  olo[base + tid + 256] = l2;
}

// ---------------- HMMA bf16-split GEMM (cp.async, fused segments) -------------
// C[M,N] = (Ahi+Alo)(Bhi+Blo)^T ~= AhiBhi + AloBhi + AhiBlo.
// Each K-chunk loads all 4 tiles via cp.async; 12 chunks, double-buffered.
template <bool RELU, bool RESID, bool SPLIT>
__global__ __launch_bounds__(256, 2) void gemm_mma_kernel(
    int N,
    const __nv_bfloat16* __restrict__ Ahi,
    const __nv_bfloat16* __restrict__ Alo,
    const __nv_bfloat16* __restrict__ Bhi,
    const __nv_bfloat16* __restrict__ Blo,
    const float* __restrict__ bias,
    const float* __restrict__ resid,
    float* __restrict__ outf,
    __nv_bfloat16* __restrict__ ohi,
    __nv_bfloat16* __restrict__ olo) {
    extern __shared__ char gsm[];
    uint32_t S0 = (uint32_t)__cvta_generic_to_shared(gsm);

    int tid = threadIdx.x;
    int lane = tid & 31;
    int wid = tid >> 5;
    int bm = blockIdx.y * BM;
    int bn = blockIdx.x * BN;

    int r0 = tid >> 2;            // 0..63
    int c4 = (tid & 3) * 8;       // 0,8,16,24

    int m0w = (wid >> 1) * 32;
    int n0w = (wid & 1) * 64;

    // per-thread global element offsets (chunk k added later)
    size_t gA0 = (size_t)(bm + r0) * KTOT + c4;
    size_t gA1 = (size_t)(bm + r0 + 64) * KTOT + c4;
    size_t gB0 = (size_t)(bn + r0) * KTOT + c4;
    size_t gB1 = (size_t)(bn + r0 + 64) * KTOT + c4;
    uint32_t s0 = (uint32_t)(r0 * LDP + c4) * 2;
    uint32_t s1 = (uint32_t)((r0 + 64) * LDP + c4) * 2;

    uint32_t a_off = ((m0w + (lane & 15)) * LDP + (lane >> 4) * 8) * 2;
    uint32_t b_off[4];
    #pragma unroll
    for (int nb = 0; nb < 4; nb++)
        b_off[nb] = ((n0w + nb * 16 + ((lane >> 4) & 1) * 8 + (lane & 7)) * LDP
                     + ((lane >> 3) & 1) * 8) * 2;

    float acc[2][8][4];
    #pragma unroll
    for (int mi = 0; mi < 2; mi++)
        #pragma unroll
        for (int ni = 0; ni < 8; ni++)
            #pragma unroll
            for (int q = 0; q < 4; q++) acc[mi][ni][q] = 0.0f;

    // prefetch chunk 0 into buffer 0
    {
        uint32_t base = S0;
        cp16(base + s0, Ahi + gA0);
        cp16(base + s1, Ahi + gA1);
        cp16(base + TILE_B + s0, Alo + gA0);
        cp16(base + TILE_B + s1, Alo + gA1);
        cp16(base + 2 * TILE_B + s0, Bhi + gB0);
        cp16(base + 2 * TILE_B + s1, Bhi + gB1);
        cp16(base + 3 * TILE_B + s0, Blo + gB0);
        cp16(base + 3 * TILE_B + s1, Blo + gB1);
        CP_COMMIT();
    }

    int buf = 0;
    #pragma unroll 1
    for (int t = 0; t < NCHUNK; t++) {
        if (t + 1 < NCHUNK) {
            int kk = (t + 1) * BKC;
            uint32_t base = S0 + (buf ^ 1) * BUFB;
            cp16(base + s0, Ahi + gA0 + kk);
            cp16(base + s1, Ahi + gA1 + kk);
            cp16(base + TILE_B + s0, Alo + gA0 + kk);
            cp16(base + TILE_B + s1, Alo + gA1 + kk);
            cp16(base + 2 * TILE_B + s0, Bhi + gB0 + kk);
            cp16(base + 2 * TILE_B + s1, Bhi + gB1 + kk);
            cp16(base + 3 * TILE_B + s0, Blo + gB0 + kk);
            cp16(base + 3 * TILE_B + s1, Blo + gB1 + kk);
            CP_COMMIT();
            CP_WAIT(1);
        } else {
            CP_WAIT(0);
        }
        __syncthreads();

        uint32_t bb = S0 + buf * BUFB;
        #pragma unroll
        for (int ks = 0; ks < 2; ks++) {
            uint32_t kb = ks * 32;
            uint32_t ah[2][4], al[2][4];
            ldsm4(ah[0][0], ah[0][1], ah[0][2], ah[0][3], bb + a_off + kb);
            ldsm4(ah[1][0], ah[1][1], ah[1][2], ah[1][3],
                  bb + a_off + 16 * LDP * 2 + kb);
            ldsm4(al[0][0], al[0][1], al[0][2], al[0][3],
                  bb + TILE_B + a_off + kb);
            ldsm4(al[1][0], al[1][1], al[1][2], al[1][3],
                  bb + TILE_B + a_off + 16 * LDP * 2 + kb);
            #pragma unroll
            for (int nb = 0; nb < 4; nb++) {
                uint32_t bh[4], bl[4];
                ldsm4(bh[0], bh[1], bh[2], bh[3],
                      bb + 2 * TILE_B + b_off[nb] + kb);
                ldsm4(bl[0], bl[1], bl[2], bl[3],
                      bb + 3 * TILE_B + b_off[nb] + kb);
                #pragma unroll
                for (int mi = 0; mi < 2; mi++) {
                    mma16816(acc[mi][2 * nb],     ah[mi][0], ah[mi][1], ah[mi][2], ah[mi][3], bh[0], bh[1]);
                    mma16816(acc[mi][2 * nb + 1], ah[mi][0], ah[mi][1], ah[mi][2], ah[mi][3], bh[2], bh[3]);
                    mma16816(acc[mi][2 * nb],     al[mi][0], al[mi][1], al[mi][2], al[mi][3], bh[0], bh[1]);
                    mma16816(acc[mi][2 * nb + 1], al[mi][0], al[mi][1], al[mi][2], al[mi][3], bh[2], bh[3]);
                    mma16816(acc[mi][2 * nb],     ah[mi][0], ah[mi][1], ah[mi][2], ah[mi][3], bl[0], bl[1]);
                    mma16816(acc[mi][2 * nb + 1], ah[mi][0], ah[mi][1], ah[mi][2], ah[mi][3], bl[2], bl[3]);
                }
            }
        }
        __syncthreads();
        buf ^= 1;
    }

    int rbase = bm + m0w + (lane >> 2);
    int cbase = bn + n0w + (lane & 3) * 2;
    #pragma unroll
    for (int mi = 0; mi < 2; mi++) {
        #pragma unroll
        for (int half = 0; half < 2; half++) {
            int row = rbase + mi * 16 + half * 8;
            #pragma unroll
            for (int ni = 0; ni < 8; ni++) {
                int col = cbase + ni * 8;
                float vx = acc[mi][ni][half * 2 + 0];
                float vy = acc[mi][ni][half * 2 + 1];
                float2 bv = *(const float2*)(bias + col);
                vx += bv.x; vy += bv.y;
                if (RESID) {
                    float2 rv = *(const float2*)(resid + (size_t)row * N + col);
                    vx += rv.x; vy += rv.y;
                }
                if (RELU) { vx = fmaxf(vx, 0.f); vy = fmaxf(vy, 0.f); }
                if (SPLIT) {
                    union { __nv_bfloat16 b[2]; uint32_t u; } H, L;
                    split1(vx, H.b[0], L.b[0]);
                    split1(vy, H.b[1], L.b[1]);
                    *(uint32_t*)(ohi + (size_t)row * N + col) = H.u;
                    *(uint32_t*)(olo + (size_t)row * N + col) = L.u;
                } else {
                    float2 o; o.x = vx; o.y = vy;
                    *(float2*)(outf + (size_t)row * N + col) = o;
                }
            }
        }
    }
}

// ---------------- HMMA flash attention ----------------------------------------
__global__ __launch_bounds__(128) void fattn_mma_kernel(
    const __nv_bfloat16* __restrict__ qh, const __nv_bfloat16* __restrict__ ql,
    __nv_bfloat16* __restrict__ ohi, __nv_bfloat16* __restrict__ olo) {
    extern __shared__ __nv_bfloat16 smb[];
    __nv_bfloat16* Qh = smb;
    __nv_bfloat16* Ql = smb + 64 * ATP;
    __nv_bfloat16* Kh = smb + 2 * 64 * ATP;
    __nv_bfloat16* Kl = smb + 3 * 64 * ATP;
    __nv_bfloat16* Vh = smb + 4 * 64 * ATP;
    __nv_bfloat16* Vl = smb + 5 * 64 * ATP;

    int qt = blockIdx.x;
    int bh = blockIdx.y;
    int b = bh / NH;
    int h = bh - b * NH;
    int hoff = h * HD;
    int q0 = qt * 64;
    int tid = threadIdx.x;
    int lane = tid & 31;
    int w = tid >> 5;
    size_t tokbase = (size_t)b * SEQ;

    #pragma unroll
    for (int i = 0; i < 4; i++) {
        int idx = tid + i * 128;
        int r = idx >> 3, c8 = (idx & 7) * 8;
        size_t off = (tokbase + q0 + r) * QKVN + hoff + c8;
        *(uint4*)&Qh[r * ATP + c8] = *(const uint4*)(qh + off);
        *(uint4*)&Ql[r * ATP + c8] = *(const uint4*)(ql + off);
    }

    uint32_t sQh = (uint32_t)__cvta_generic_to_shared(Qh);
    uint32_t sQl = (uint32_t)__cvta_generic_to_shared(Ql);
    uint32_t sKh = (uint32_t)__cvta_generic_to_shared(Kh);
    uint32_t sKl = (uint32_t)__cvta_generic_to_shared(Kl);
    uint32_t sVh = (uint32_t)__cvta_generic_to_shared(Vh);
    uint32_t sVl = (uint32_t)__cvta_generic_to_shared(Vl);

    uint32_t a_byte = ((w * 16 + (lane & 15)) * ATP + (lane >> 4) * 8) * 2;
    uint32_t kb_byte[4];
    #pragma unroll
    for (int nb = 0; nb < 4; nb++)
        kb_byte[nb] = ((nb * 16 + ((lane >> 4) & 1) * 8 + (lane & 7)) * ATP
                       + ((lane >> 3) & 1) * 8) * 2;
    uint32_t v_row = ((lane >> 3) & 1) * 8 + (lane & 7);
    uint32_t v_col = ((lane >> 4) & 1) * 8;

    float m0 = -INFINITY, m1 = -INFINITY, l0 = 0.f, l1 = 0.f;
    float oacc[8][4];
    #pragma unroll
    for (int i = 0; i < 8; i++)
        #pragma unroll
        for (int q = 0; q < 4; q++) oacc[i][q] = 0.f;

    const float scale = rsqrtf((float)CDIM);

    #pragma unroll 1
    for (int st = 0; st <= qt; st++) {
        int s0 = st * 64;
        __syncthreads();
        #pragma unroll
        for (int i = 0; i < 4; i++) {
            int idx = tid + i * 128;
            int r = idx >> 3, c8 = (idx & 7) * 8;
            size_t off = (tokbase + s0 + r) * QKVN + hoff + c8;
            *(uint4*)&Kh[r * ATP + c8] = *(const uint4*)(qh + off + CDIM);
            *(uint4*)&Kl[r * ATP + c8] = *(const uint4*)(ql + off + CDIM);
            *(uint4*)&Vh[r * ATP + c8] = *(const uint4*)(qh + off + 2 * CDIM);
            *(uint4*)&Vl[r * ATP + c8] = *(const uint4*)(ql + off + 2 * CDIM);
        }
        __syncthreads();

        float sacc[8][4];
        #pragma unroll
        for (int i = 0; i < 8; i++)
            #pragma unroll
            for (int q = 0; q < 4; q++) sacc[i][q] = 0.f;

        #pragma unroll
        for (int ks = 0; ks < 4; ks++) {
            uint32_t kb = ks * 32;
            uint32_t ah[4], al[4];
            ldsm4(ah[0], ah[1], ah[2], ah[3], sQh + a_byte + kb);
            ldsm4(al[0], al[1], al[2], al[3], sQl + a_byte + kb);
            #pragma unroll
            for (int nb = 0; nb < 4; nb++) {
                uint32_t kh[4], kl[4];
                ldsm4(kh[0], kh[1], kh[2], kh[3], sKh + kb_byte[nb] + kb);
                ldsm4(kl[0], kl[1], kl[2], kl[3], sKl + kb_byte[nb] + kb);
                mma16816(sacc[2 * nb],     ah[0], ah[1], ah[2], ah[3], kh[0], kh[1]);
                mma16816(sacc[2 * nb + 1], ah[0], ah[1], ah[2], ah[3], kh[2], kh[3]);
                mma16816(sacc[2 * nb],     al[0], al[1], al[2], al[3], kh[0], kh[1]);
                mma16816(sacc[2 * nb + 1], al[0], al[1], al[2], al[3], kh[2], kh[3]);
                mma16816(sacc[2 * nb],     ah[0], ah[1], ah[2], ah[3], kl[0], kl[1]);
                mma16816(sacc[2 * nb + 1], ah[0], ah[1], ah[2], ah[3], kl[2], kl[3]);
            }
        }

        #pragma unroll
        for (int nf = 0; nf < 8; nf++)
            #pragma unroll
            for (int q = 0; q < 4; q++) sacc[nf][q] *= scale;

        if (st == qt) {
            int lr0 = w * 16 + (lane >> 2);
            #pragma unroll
            for (int nf = 0; nf < 8; nf++) {
                #pragma unroll
                for (int q = 0; q < 4; q++) {
                    int col = nf * 8 + (lane & 3) * 2 + (q & 1);
                    int row = lr0 + ((q >> 1) << 3);
                    if (col > row) sacc[nf][q] = -INFINITY;
                }
            }
        }

        float mx0 = -INFINITY, mx1 = -INFINITY;
        #pragma unroll
        for (int nf = 0; nf < 8; nf++) {
            mx0 = fmaxf(mx0, fmaxf(sacc[nf][0], sacc[nf][1]));
            mx1 = fmaxf(mx1, fmaxf(sacc[nf][2], sacc[nf][3]));
        }
        mx0 = fmaxf(mx0, __shfl_xor_sync(0xFFFFFFFFu, mx0, 1));
        mx0 = fmaxf(mx0, __shfl_xor_sync(0xFFFFFFFFu, mx0, 2));
        mx1 = fmaxf(mx1, __shfl_xor_sync(0xFFFFFFFFu, mx1, 1));
        mx1 = fmaxf(mx1, __shfl_xor_sync(0xFFFFFFFFu, mx1, 2));

        float mn0 = fmaxf(m0, mx0), mn1 = fmaxf(m1, mx1);
        float c0 = __expf(m0 - mn0), c1 = __expf(m1 - mn1);
        m0 = mn0; m1 = mn1;

        float rs0 = 0.f, rs1 = 0.f;
        #pragma unroll
        for (int nf = 0; nf < 8; nf++) {
            sacc[nf][0] = __expf(sacc[nf][0] - mn0); rs0 += sacc[nf][0];
            sacc[nf][1] = __expf(sacc[nf][1] - mn0); rs0 += sacc[nf][1];
            sacc[nf][2] = __expf(sacc[nf][2] - mn1); rs1 += sacc[nf][2];
            sacc[nf][3] = __expf(sacc[nf][3] - mn1); rs1 += sacc[nf][3];
        }
        rs0 += __shfl_xor_sync(0xFFFFFFFFu, rs0, 1);
        rs0 += __shfl_xor_sync(0xFFFFFFFFu, rs0, 2);
        rs1 += __shfl_xor_sync(0xFFFFFFFFu, rs1, 1);
        rs1 += __shfl_xor_sync(0xFFFFFFFFu, rs1, 2);
        l0 = l0 * c0 + rs0;
        l1 = l1 * c1 + rs1;

        #pragma unroll
        for (int nf = 0; nf < 8; nf++) {
            oacc[nf][0] *= c0; oacc[nf][1] *= c0;
            oacc[nf][2] *= c1; oacc[nf][3] *= c1;
        }

        #pragma unroll
        for (int ks = 0; ks < 4; ks++) {
            uint32_t ph[4], pl[4];
            #pragma unroll
            for (int half = 0; half < 2; half++) {
                int f = 2 * ks + half;
                uint32_t h0 = pack2(sacc[f][0], sacc[f][1]);
                uint32_t h1 = pack2(sacc[f][2], sacc[f][3]);
                ph[2 * half + 0] = h0;
                ph[2 * half + 1] = h1;
                pl[2 * half + 0] = pack2(sacc[f][0] - bf16lo_f(h0),
                                         sacc[f][1] - bf16hi_f(h0));
                pl[2 * half + 1] = pack2(sacc[f][2] - bf16lo_f(h1),
                                         sacc[f][3] - bf16hi_f(h1));
            }
            #pragma unroll
            for (int nb2 = 0; nb2 < 4; nb2++) {
                uint32_t voff = ((ks * 16 + v_row) * ATP + nb2 * 16 + v_col) * 2;
                uint32_t vh[4], vl[4];
                ldsm4t(vh[0], vh[1], vh[2], vh[3], sVh + voff);
                ldsm4t(vl[0], vl[1], vl[2], vl[3], sVl + voff);
                mma16816(oacc[2 * nb2],     ph[0], ph[1], ph[2], ph[3], vh[0], vh[1]);
                mma16816(oacc[2 * nb2 + 1], ph[0], ph[1], ph[2], ph[3], vh[2], vh[3]);
                mma16816(oacc[2 * nb2],     pl[0], pl[1], pl[2], pl[3], vh[0], vh[1]);
                mma16816(oacc[2 * nb2 + 1], pl[0], pl[1], pl[2], pl[3], vh[2], vh[3]);
                mma16816(oacc[2 * nb2],     ph[0], ph[1], ph[2], ph[3], vl[0], vl[1]);
                mma16816(oacc[2 * nb2 + 1], ph[0], ph[1], ph[2], ph[3], vl[2], vl[3]);
            }
        }
    }

    float i0 = 1.0f / l0, i1 = 1.0f / l1;
    int row0 = q0 + w * 16 + (lane >> 2);
    #pragma unroll
    for (int nf = 0; nf < 8; nf++) {
        int col = hoff + nf * 8 + (lane & 3) * 2;
        size_t o0 = (tokbase + row0) * CDIM + col;
        size_t o1 = (tokbase + row0 + 8) * CDIM + col;
        union { __nv_bfloat16 b[2]; uint32_t u; } H, L;
        split1(oacc[nf][0] * i0, H.b[0], L.b[0]);
        split1(oacc[nf][1] * i0, H.b[1], L.b[1]);
        *(uint32_t*)(ohi + o0) = H.u;
        *(uint32_t*)(olo + o0) = L.u;
        split1(oacc[nf][2] * i1, H.b[0], L.b[0]);
        split1(oacc[nf][3] * i1, H.b[1], L.b[1]);
        *(uint32_t*)(ohi + o1) = H.u;
        *(uint32_t*)(olo + o1) = L.u;
    }
}

// ---------------- launch ------------------------------------------------------
extern "C" void kernel_launch(void* const* d_in, const int* in_sizes, int n_in,
                              void* d_out, int out_size) {
    const float* x    = (const float*)d_in[0];
    const float* Wq   = (const float*)d_in[1];
    const float* bq   = (const float*)d_in[2];
    const float* Wk   = (const float*)d_in[3];
    const float* bk   = (const float*)d_in[4];
    const float* Wv   = (const float*)d_in[5];
    const float* bv   = (const float*)d_in[6];
    const float* Wp   = (const float*)d_in[7];
    const float* bp   = (const float*)d_in[8];
    const float* W1   = (const float*)d_in[9];
    const float* b1   = (const float*)d_in[10];
    const float* W2   = (const float*)d_in[11];
    const float* b2   = (const float*)d_in[12];
    const float* ln1g = (const float*)d_in[13];
    const float* ln1b = (const float*)d_in[14];
    const float* ln2g = (const float*)d_in[15];
    const float* ln2b = (const float*)d_in[16];

    float *x2, *bqkv;
    __nv_bfloat16 *qkvh, *qkvl, *ahi, *alo, *f1hi, *f1lo;
    __nv_bfloat16 *wqh, *wql, *wph, *wpl, *w1h, *w1l, *w2h, *w2l;
    cudaGetSymbolAddress((void**)&qkvh, g_qkvhi);
    cudaGetSymbolAddress((void**)&qkvl, g_qkvlo);
    cudaGetSymbolAddress((void**)&x2,   g_x2);
    cudaGetSymbolAddress((void**)&bqkv, g_bqkv);
    cudaGetSymbolAddress((void**)&ahi,  g_ahi);
    cudaGetSymbolAddress((void**)&alo,  g_alo);
    cudaGetSymbolAddress((void**)&f1hi, g_f1hi);
    cudaGetSymbolAddress((void**)&f1lo, g_f1lo);
    cudaGetSymbolAddress((void**)&wqh,  g_wqkvhi);
    cudaGetSymbolAddress((void**)&wql,  g_wqkvlo);
    cudaGetSymbolAddress((void**)&wph,  g_wphi);
    cudaGetSymbolAddress((void**)&wpl,  g_wplo);
    cudaGetSymbolAddress((void**)&w1h,  g_w1hi);
    cudaGetSymbolAddress((void**)&w1l,  g_w1lo);
    cudaGetSymbolAddress((void**)&w2h,  g_w2hi);
    cudaGetSymbolAddress((void**)&w2l,  g_w2lo);

    const int attn_smem = 6 * 64 * ATP * (int)sizeof(__nv_bfloat16);  // 55296
    cudaFuncSetAttribute(fattn_mma_kernel,
                         cudaFuncAttributeMaxDynamicSharedMemorySize, attn_smem);
    cudaFuncSetAttribute(gemm_mma_kernel<false, false, true>,
                         cudaFuncAttributeMaxDynamicSharedMemorySize, GSMEM);
    cudaFuncSetAttribute(gemm_mma_kernel<false, true, false>,
                         cudaFuncAttributeMaxDynamicSharedMemorySize, GSMEM);
    cudaFuncSetAttribute(gemm_mma_kernel<true, false, true>,
                         cudaFuncAttributeMaxDynamicSharedMemorySize, GSMEM);

    // weight conversions
    wsplit_qkv_kernel<<<(QKVN * CDIM + 255) / 256, 256>>>(Wq, Wk, Wv, bq, bk, bv,
                                                          wqh, wql, bqkv);
    {
        dim3 grid((CDIM * CDIM + 255) / 256, 3);
        wsplit_t3_kernel<<<grid, 256>>>(Wp, W1, W2, wph, wpl, w1h, w1l, w2h, w2l);
    }

    // LN1 -> bf16 hi/lo
    ln_split_kernel<<<BT, 128>>>(x, ln1g, ln1b, ahi, alo);

    // QKV projection -> bf16 hi/lo
    {
        dim3 grid(QKVN / BN, BT / BM);
        gemm_mma_kernel<false, false, true><<<grid, 256, GSMEM>>>(
            QKVN, ahi, alo, wqh, wql, bqkv, nullptr, nullptr, qkvh, qkvl);
    }
    // HMMA flash attention -> bf16 hi/lo (reuses ahi/alo)
    {
        dim3 grid(SEQ / 64, BATCH * NH);
        fattn_mma_kernel<<<grid, 128, attn_smem>>>(qkvh, qkvl, ahi, alo);
    }
    // output projection + residual(x) -> x2 fp32
    {
        dim3 grid(CDIM / BN, BT / BM);
        gemm_mma_kernel<false, true, false><<<grid, 256, GSMEM>>>(
            CDIM, ahi, alo, wph, wpl, bp, x, x2, nullptr, nullptr);
        // LN2 -> bf16 hi/lo
        ln_split_kernel<<<BT, 128>>>(x2, ln2g, ln2b, ahi, alo);
        // FF1 + ReLU -> bf16 hi/lo
        gemm_mma_kernel<true, false, true><<<grid, 256, GSMEM>>>(
            CDIM, ahi, alo, w1h, w1l, b1, nullptr, nullptr, f1hi, f1lo);
        // FF2 + residual(x2) -> d_out fp32
        gemm_mma_kernel<false, true, false><<<grid, 256, GSMEM>>>(
            CDIM, f1hi, f1lo, w2h, w2l, b2, x2, (float*)d_out, nullptr, nullptr);
    }
}

// round 16
// speedup vs baseline: 4.4581x; 1.0072x over previous
#include <cuda_runtime.h>
#include <cuda_bf16.h>
#include <math.h>
#include <stdint.h>

// Problem constants
#define BATCH 64
#define SEQ   256
#define BT    16384      // BATCH*SEQ
#define CDIM  384
#define NH    6
#define HD    64
#define QKVN  1152       // 3*CDIM

// GEMM tiling (HMMA mma.sync path)
#define BM  128
#define BN  128
#define BKC 32
#define LDP 40           // smem row pitch in bf16 elems
#define KTOT 384
#define NCHUNK (KTOT / BKC)   // 12

#define TILE_B (BM * LDP * 2)     // bytes per tile (10240)
#define BUFB   (4 * TILE_B)       // bytes per buffer (Ahi,Alo,Bhi,Blo)
#define GSMEM  (2 * BUFB)         // 81920 bytes dynamic smem

// attention smem pitch (bf16 elems)
#define ATP 72

// ---------------- scratch (static device globals; no allocation) ------------
__device__ __nv_bfloat16  g_qkvhi[BT * QKVN];
__device__ __nv_bfloat16  g_qkvlo[BT * QKVN];
__device__ float          g_x2  [BT * CDIM];
__device__ __nv_bfloat16  g_ahi [BT * CDIM];
__device__ __nv_bfloat16  g_alo [BT * CDIM];
__device__ __nv_bfloat16  g_f1hi[BT * CDIM];
__device__ __nv_bfloat16  g_f1lo[BT * CDIM];
__device__ __nv_bfloat16  g_wqkvhi[QKVN * CDIM];  // [N][K] K-major
__device__ __nv_bfloat16  g_wqkvlo[QKVN * CDIM];
__device__ __nv_bfloat16  g_wphi[CDIM * CDIM];
__device__ __nv_bfloat16  g_wplo[CDIM * CDIM];
__device__ __nv_bfloat16  g_w1hi[CDIM * CDIM];
__device__ __nv_bfloat16  g_w1lo[CDIM * CDIM];
__device__ __nv_bfloat16  g_w2hi[CDIM * CDIM];
__device__ __nv_bfloat16  g_w2lo[CDIM * CDIM];
__device__ float          g_bqkv[QKVN];

// ---------------- helpers ----------------------------------------------------
__device__ __forceinline__ void split1(float v, __nv_bfloat16& h, __nv_bfloat16& l) {
    h = __float2bfloat16(v);
    l = __float2bfloat16(v - __bfloat162float(h));
}

__device__ __forceinline__ void ldsm4(uint32_t& r0, uint32_t& r1,
                                      uint32_t& r2, uint32_t& r3, uint32_t a) {
    asm volatile("ldmatrix.sync.aligned.m8n8.x4.shared.b16 {%0,%1,%2,%3}, [%4];"
                 : "=r"(r0), "=r"(r1), "=r"(r2), "=r"(r3) : "r"(a));
}

__device__ __forceinline__ void ldsm4t(uint32_t& r0, uint32_t& r1,
                                       uint32_t& r2, uint32_t& r3, uint32_t a) {
    asm volatile("ldmatrix.sync.aligned.m8n8.x4.trans.shared.b16 {%0,%1,%2,%3}, [%4];"
                 : "=r"(r0), "=r"(r1), "=r"(r2), "=r"(r3) : "r"(a));
}

__device__ __forceinline__ void mma16816(float* c,
                                         uint32_t a0, uint32_t a1,
                                         uint32_t a2, uint32_t a3,
                                         uint32_t b0, uint32_t b1) {
    asm volatile(
        "mma.sync.aligned.m16n8k16.row.col.f32.bf16.bf16.f32 "
        "{%0,%1,%2,%3}, {%4,%5,%6,%7}, {%8,%9}, {%0,%1,%2,%3};"
        : "+f"(c[0]), "+f"(c[1]), "+f"(c[2]), "+f"(c[3])
        : "r"(a0), "r"(a1), "r"(a2), "r"(a3), "r"(b0), "r"(b1));
}

__device__ __forceinline__ void cp16(uint32_t dst, const void* src) {
    asm volatile("cp.async.cg.shared.global [%0], [%1], 16;"
                 :: "r"(dst), "l"(src));
}
#define CP_COMMIT() asm volatile("cp.async.commit_group;" ::: "memory")
#define CP_WAIT(n)  asm volatile("cp.async.wait_group %0;" :: "n"(n) : "memory")

__device__ __forceinline__ uint32_t pack2(float lo, float hi) {
    uint32_t r;
    asm("cvt.rn.bf16x2.f32 %0, %1, %2;" : "=r"(r) : "f"(hi), "f"(lo));
    return r;
}
__device__ __forceinline__ float bf16lo_f(uint32_t u) {
    return __uint_as_float(u << 16);
}
__device__ __forceinline__ float bf16hi_f(uint32_t u) {
    return __uint_as_float(u & 0xFFFF0000u);
}

// ---------------- weight conversion kernels ----------------------------------
__global__ void wsplit_qkv_kernel(const float* __restrict__ Wq,
                                  const float* __restrict__ Wk,
                                  const float* __restrict__ Wv,
                                  const float* __restrict__ bq,
                                  const float* __restrict__ bk,
                                  const float* __restrict__ bv,
                                  __nv_bfloat16* __restrict__ whi,
                                  __nv_bfloat16* __restrict__ wlo,
                                  float* __restrict__ bqkv) {
    int idx = blockIdx.x * blockDim.x + threadIdx.x;
    if (idx < QKVN * CDIM) {
        int n = idx / CDIM;
        int c = idx - n * CDIM;
        int nn = n % CDIM;
        int h = nn / HD;
        int d = nn - h * HD;
        const float* W = (n < CDIM) ? Wq : ((n < 2 * CDIM) ? Wk : Wv);
        float v = W[((size_t)h * CDIM + c) * HD + d];
        __nv_bfloat16 hi, lo;
        split1(v, hi, lo);
        whi[idx] = hi;
        wlo[idx] = lo;
    }
    if (idx < QKVN) {
        int nn = idx % CDIM;
        const float* bb = (idx < CDIM) ? bq : ((idx < 2 * CDIM) ? bk : bv);
        bqkv[idx] = bb[nn];
    }
}

// 3 weight matrices in one launch: blockIdx.y selects Wp/W1/W2
__global__ void wsplit_t3_kernel(const float* __restrict__ Wp,
                                 const float* __restrict__ W1,
                                 const float* __restrict__ W2,
                                 __nv_bfloat16* __restrict__ ph,
                                 __nv_bfloat16* __restrict__ pl,
                                 __nv_bfloat16* __restrict__ h1,
                                 __nv_bfloat16* __restrict__ l1,
                                 __nv_bfloat16* __restrict__ h2,
                                 __nv_bfloat16* __restrict__ l2) {
    int idx = blockIdx.x * blockDim.x + threadIdx.x;
    if (idx >= CDIM * CDIM) return;
    const float* src = (blockIdx.y == 0) ? Wp : ((blockIdx.y == 1) ? W1 : W2);
    __nv_bfloat16* dh = (blockIdx.y == 0) ? ph : ((blockIdx.y == 1) ? h1 : h2);
    __nv_bfloat16* dl = (blockIdx.y == 0) ? pl : ((blockIdx.y == 1) ? l1 : l2);
    int n = idx / CDIM;
    int k = idx - n * CDIM;
    float v = src[(size_t)k * CDIM + n];
    __nv_bfloat16 hi, lo;
    split1(v, hi, lo);
    dh[idx] = hi;
    dl[idx] = lo;
}

// ---------------- LayerNorm + bf16 split -------------------------------------
__global__ __launch_bounds__(128) void ln_split_kernel(
    const float* __restrict__ x, const float* __restrict__ g,
    const float* __restrict__ b,
    __nv_bfloat16* __restrict__ ohi, __nv_bfloat16* __restrict__ olo) {
    __shared__ float red1[4];
    __shared__ float red2[4];
    int row = blockIdx.x;
    int tid = threadIdx.x;
    const float* xr = x + (size_t)row * CDIM;

    float v0 = xr[tid], v1 = xr[tid + 128], v2 = xr[tid + 256];
    float s = v0 + v1 + v2;
    #pragma unroll
    for (int o = 16; o > 0; o >>= 1) s += __shfl_xor_sync(0xFFFFFFFFu, s, o);
    if ((tid & 31) == 0) red1[tid >> 5] = s;
    __syncthreads();
    float mu = (red1[0] + red1[1] + red1[2] + red1[3]) * (1.0f / CDIM);

    float d0 = v0 - mu, d1 = v1 - mu, d2 = v2 - mu;
    float sq = d0 * d0 + d1 * d1 + d2 * d2;
    #pragma unroll
    for (int o = 16; o > 0; o >>= 1) sq += __shfl_xor_sync(0xFFFFFFFFu, sq, o);
    if ((tid & 31) == 0) red2[tid >> 5] = sq;
    __syncthreads();
    float var = (red2[0] + red2[1] + red2[2] + red2[3]) * (1.0f / CDIM);
    float rs = rsqrtf(var + 1e-5f);

    size_t base = (size_t)row * CDIM;
    float y0 = d0 * rs * g[tid]       + b[tid];
    float y1 = d1 * rs * g[tid + 128] + b[tid + 128];
    float y2 = d2 * rs * g[tid + 256] + b[tid + 256];
    __nv_bfloat16 h0, l0, h1, l1, h2, l2;
    split1(y0, h0, l0); split1(y1, h1, l1); split1(y2, h2, l2);
    ohi[base + tid] = h0;        olo[base + tid] = l0;
    ohi[base + tid + 128] = h1;  olo[base + tid + 128] = l1;
    ohi[base + tid + 256] = h2;  olo[base + tid + 256] = l2;
}

// ---------------- HMMA bf16-split GEMM (cp.async, term-major MMA order) -------
// C[M,N] = (Ahi+Alo)(Bhi+Blo)^T ~= AhiBhi + AloBhi + AhiBlo.
// Per ks-step: preload ALL fragments, then issue the 48 MMAs term-major so the
// 16 accumulators form 16 independent chains (reuse distance 16, not 1).
template <bool RELU, bool RESID, bool SPLIT>
__global__ __launch_bounds__(256, 2) void gemm_mma_kernel(
    int N,
    const __nv_bfloat16* __restrict__ Ahi,
    const __nv_bfloat16* __restrict__ Alo,
    const __nv_bfloat16* __restrict__ Bhi,
    const __nv_bfloat16* __restrict__ Blo,
    const float* __restrict__ bias,
    const float* __restrict__ resid,
    float* __restrict__ outf,
    __nv_bfloat16* __restrict__ ohi,
    __nv_bfloat16* __restrict__ olo) {
    extern __shared__ char gsm[];
    uint32_t S0 = (uint32_t)__cvta_generic_to_shared(gsm);

    int tid = threadIdx.x;
    int lane = tid & 31;
    int wid = tid >> 5;
    int bm = blockIdx.y * BM;
    int bn = blockIdx.x * BN;

    int r0 = tid >> 2;            // 0..63
    int c4 = (tid & 3) * 8;       // 0,8,16,24

    int m0w = (wid >> 1) * 32;
    int n0w = (wid & 1) * 64;

    size_t gA0 = (size_t)(bm + r0) * KTOT + c4;
    size_t gA1 = (size_t)(bm + r0 + 64) * KTOT + c4;
    size_t gB0 = (size_t)(bn + r0) * KTOT + c4;
    size_t gB1 = (size_t)(bn + r0 + 64) * KTOT + c4;
    uint32_t s0 = (uint32_t)(r0 * LDP + c4) * 2;
    uint32_t s1 = (uint32_t)((r0 + 64) * LDP + c4) * 2;

    uint32_t a_off = ((m0w + (lane & 15)) * LDP + (lane >> 4) * 8) * 2;
    uint32_t b_off[4];
    #pragma unroll
    for (int nb = 0; nb < 4; nb++)
        b_off[nb] = ((n0w + nb * 16 + ((lane >> 4) & 1) * 8 + (lane & 7)) * LDP
                     + ((lane >> 3) & 1) * 8) * 2;

    float acc[2][8][4];
    #pragma unroll
    for (int mi = 0; mi < 2; mi++)
        #pragma unroll
        for (int ni = 0; ni < 8; ni++)
            #pragma unroll
            for (int q = 0; q < 4; q++) acc[mi][ni][q] = 0.0f;

    // prefetch chunk 0 into buffer 0
    {
        uint32_t base = S0;
        cp16(base + s0, Ahi + gA0);
        cp16(base + s1, Ahi + gA1);
        cp16(base + TILE_B + s0, Alo + gA0);
        cp16(base + TILE_B + s1, Alo + gA1);
        cp16(base + 2 * TILE_B + s0, Bhi + gB0);
        cp16(base + 2 * TILE_B + s1, Bhi + gB1);
        cp16(base + 3 * TILE_B + s0, Blo + gB0);
        cp16(base + 3 * TILE_B + s1, Blo + gB1);
        CP_COMMIT();
    }

    int buf = 0;
    #pragma unroll 1
    for (int t = 0; t < NCHUNK; t++) {
        if (t + 1 < NCHUNK) {
            int kk = (t + 1) * BKC;
            uint32_t base = S0 + (buf ^ 1) * BUFB;
            cp16(base + s0, Ahi + gA0 + kk);
            cp16(base + s1, Ahi + gA1 + kk);
            cp16(base + TILE_B + s0, Alo + gA0 + kk);
            cp16(base + TILE_B + s1, Alo + gA1 + kk);
            cp16(base + 2 * TILE_B + s0, Bhi + gB0 + kk);
            cp16(base + 2 * TILE_B + s1, Bhi + gB1 + kk);
            cp16(base + 3 * TILE_B + s0, Blo + gB0 + kk);
            cp16(base + 3 * TILE_B + s1, Blo + gB1 + kk);
            CP_COMMIT();
            CP_WAIT(1);
        } else {
            CP_WAIT(0);
        }
        __syncthreads();

        uint32_t bb = S0 + buf * BUFB;
        #pragma unroll
        for (int ks = 0; ks < 2; ks++) {
            uint32_t kb = ks * 32;
            // preload ALL fragments for this k16 step
            uint32_t ah[2][4], al[2][4];
            ldsm4(ah[0][0], ah[0][1], ah[0][2], ah[0][3], bb + a_off + kb);
            ldsm4(ah[1][0], ah[1][1], ah[1][2], ah[1][3],
                  bb + a_off + 16 * LDP * 2 + kb);
            ldsm4(al[0][0], al[0][1], al[0][2], al[0][3],
                  bb + TILE_B + a_off + kb);
            ldsm4(al[1][0], al[1][1], al[1][2], al[1][3],
                  bb + TILE_B + a_off + 16 * LDP * 2 + kb);
            uint32_t bh[4][4], bl[4][4];
            #pragma unroll
            for (int nb = 0; nb < 4; nb++) {
                ldsm4(bh[nb][0], bh[nb][1], bh[nb][2], bh[nb][3],
                      bb + 2 * TILE_B + b_off[nb] + kb);
                ldsm4(bl[nb][0], bl[nb][1], bl[nb][2], bl[nb][3],
                      bb + 3 * TILE_B + b_off[nb] + kb);
            }
            // term 1: Ahi * Bhi  (16 independent accumulators)
            #pragma unroll
            for (int mi = 0; mi < 2; mi++)
                #pragma unroll
                for (int nb = 0; nb < 4; nb++) {
                    mma16816(acc[mi][2 * nb],     ah[mi][0], ah[mi][1], ah[mi][2], ah[mi][3], bh[nb][0], bh[nb][1]);
                    mma16816(acc[mi][2 * nb + 1], ah[mi][0], ah[mi][1], ah[mi][2], ah[mi][3], bh[nb][2], bh[nb][3]);
                }
            // term 2: Alo * Bhi
            #pragma unroll
            for (int mi = 0; mi < 2; mi++)
                #pragma unroll
                for (int nb = 0; nb < 4; nb++) {
                    mma16816(acc[mi][2 * nb],     al[mi][0], al[mi][1], al[mi][2], al[mi][3], bh[nb][0], bh[nb][1]);
                    mma16816(acc[mi][2 * nb + 1], al[mi][0], al[mi][1], al[mi][2], al[mi][3], bh[nb][2], bh[nb][3]);
                }
            // term 3: Ahi * Blo
            #pragma unroll
            for (int mi = 0; mi < 2; mi++)
                #pragma unroll
                for (int nb = 0; nb < 4; nb++) {
                    mma16816(acc[mi][2 * nb],     ah[mi][0], ah[mi][1], ah[mi][2], ah[mi][3], bl[nb][0], bl[nb][1]);
                    mma16816(acc[mi][2 * nb + 1], ah[mi][0], ah[mi][1], ah[mi][2], ah[mi][3], bl[nb][2], bl[nb][3]);
                }
        }
        __syncthreads();
        buf ^= 1;
    }

    int rbase = bm + m0w + (lane >> 2);
    int cbase = bn + n0w + (lane & 3) * 2;
    #pragma unroll
    for (int mi = 0; mi < 2; mi++) {
        #pragma unroll
        for (int half = 0; half < 2; half++) {
            int row = rbase + mi * 16 + half * 8;
            #pragma unroll
            for (int ni = 0; ni < 8; ni++) {
                int col = cbase + ni * 8;
                float vx = acc[mi][ni][half * 2 + 0];
                float vy = acc[mi][ni][half * 2 + 1];
                float2 bv = *(const float2*)(bias + col);
                vx += bv.x; vy += bv.y;
                if (RESID) {
                    float2 rv = *(const float2*)(resid + (size_t)row * N + col);
                    vx += rv.x; vy += rv.y;
                }
                if (RELU) { vx = fmaxf(vx, 0.f); vy = fmaxf(vy, 0.f); }
                if (SPLIT) {
                    union { __nv_bfloat16 b[2]; uint32_t u; } H, L;
                    split1(vx, H.b[0], L.b[0]);
                    split1(vy, H.b[1], L.b[1]);
                    *(uint32_t*)(ohi + (size_t)row * N + col) = H.u;
                    *(uint32_t*)(olo + (size_t)row * N + col) = L.u;
                } else {
                    float2 o; o.x = vx; o.y = vy;
                    *(float2*)(outf + (size_t)row * N + col) = o;
                }
            }
        }
    }
}

// ---------------- HMMA flash attention ----------------------------------------
__global__ __launch_bounds__(128) void fattn_mma_kernel(
    const __nv_bfloat16* __restrict__ qh, const __nv_bfloat16* __restrict__ ql,
    __nv_bfloat16* __restrict__ ohi, __nv_bfloat16* __restrict__ olo) {
    extern __shared__ __nv_bfloat16 smb[];
    __nv_bfloat16* Qh = smb;
    __nv_bfloat16* Ql = smb + 64 * ATP;
    __nv_bfloat16* Kh = smb + 2 * 64 * ATP;
    __nv_bfloat16* Kl = smb + 3 * 64 * ATP;
    __nv_bfloat16* Vh = smb + 4 * 64 * ATP;
    __nv_bfloat16* Vl = smb + 5 * 64 * ATP;

    int qt = blockIdx.x;
    int bh = blockIdx.y;
    int b = bh / NH;
    int h = bh - b * NH;
    int hoff = h * HD;
    int q0 = qt * 64;
    int tid = threadIdx.x;
    int lane = tid & 31;
    int w = tid >> 5;
    size_t tokbase = (size_t)b * SEQ;

    #pragma unroll
    for (int i = 0; i < 4; i++) {
        int idx = tid + i * 128;
        int r = idx >> 3, c8 = (idx & 7) * 8;
        size_t off = (tokbase + q0 + r) * QKVN + hoff + c8;
        *(uint4*)&Qh[r * ATP + c8] = *(const uint4*)(qh + off);
        *(uint4*)&Ql[r * ATP + c8] = *(const uint4*)(ql + off);
    }

    uint32_t sQh = (uint32_t)__cvta_generic_to_shared(Qh);
    uint32_t sQl = (uint32_t)__cvta_generic_to_shared(Ql);
    uint32_t sKh = (uint32_t)__cvta_generic_to_shared(Kh);
    uint32_t sKl = (uint32_t)__cvta_generic_to_shared(Kl);
    uint32_t sVh = (uint32_t)__cvta_generic_to_shared(Vh);
    uint32_t sVl = (uint32_t)__cvta_generic_to_shared(Vl);

    uint32_t a_byte = ((w * 16 + (lane & 15)) * ATP + (lane >> 4) * 8) * 2;
    uint32_t kb_byte[4];
    #pragma unroll
    for (int nb = 0; nb < 4; nb++)
        kb_byte[nb] = ((nb * 16 + ((lane >> 4) & 1) * 8 + (lane & 7)) * ATP
                       + ((lane >> 3) & 1) * 8) * 2;
    uint32_t v_row = ((lane >> 3) & 1) * 8 + (lane & 7);
    uint32_t v_col = ((lane >> 4) & 1) * 8;

    float m0 = -INFINITY, m1 = -INFINITY, l0 = 0.f, l1 = 0.f;
    float oacc[8][4];
    #pragma unroll
    for (int i = 0; i < 8; i++)
        #pragma unroll
        for (int q = 0; q < 4; q++) oacc[i][q] = 0.f;

    const float scale = rsqrtf((float)CDIM);

    #pragma unroll 1
    for (int st = 0; st <= qt; st++) {
        int s0 = st * 64;
        __syncthreads();
        #pragma unroll
        for (int i = 0; i < 4; i++) {
            int idx = tid + i * 128;
            int r = idx >> 3, c8 = (idx & 7) * 8;
            size_t off = (tokbase + s0 + r) * QKVN + hoff + c8;
            *(uint4*)&Kh[r * ATP + c8] = *(const uint4*)(qh + off + CDIM);
            *(uint4*)&Kl[r * ATP + c8] = *(const uint4*)(ql + off + CDIM);
            *(uint4*)&Vh[r * ATP + c8] = *(const uint4*)(qh + off + 2 * CDIM);
            *(uint4*)&Vl[r * ATP + c8] = *(const uint4*)(ql + off + 2 * CDIM);
        }
        __syncthreads();

        float sacc[8][4];
        #pragma unroll
        for (int i = 0; i < 8; i++)
            #pragma unroll
            for (int q = 0; q < 4; q++) sacc[i][q] = 0.f;

        #pragma unroll
        for (int ks = 0; ks < 4; ks++) {
            uint32_t kb = ks * 32;
            uint32_t ah[4], al[4];
            ldsm4(ah[0], ah[1], ah[2], ah[3], sQh + a_byte + kb);
            ldsm4(al[0], al[1], al[2], al[3], sQl + a_byte + kb);
            uint32_t kh[4][4], kl[4][4];
            #pragma unroll
            for (int nb = 0; nb < 4; nb++) {
                ldsm4(kh[nb][0], kh[nb][1], kh[nb][2], kh[nb][3], sKh + kb_byte[nb] + kb);
                ldsm4(kl[nb][0], kl[nb][1], kl[nb][2], kl[nb][3], sKl + kb_byte[nb] + kb);
            }
            #pragma unroll
            for (int nb = 0; nb < 4; nb++) {
                mma16816(sacc[2 * nb],     ah[0], ah[1], ah[2], ah[3], kh[nb][0], kh[nb][1]);
                mma16816(sacc[2 * nb + 1], ah[0], ah[1], ah[2], ah[3], kh[nb][2], kh[nb][3]);
            }
            #pragma unroll
            for (int nb = 0; nb < 4; nb++) {
                mma16816(sacc[2 * nb],     al[0], al[1], al[2], al[3], kh[nb][0], kh[nb][1]);
                mma16816(sacc[2 * nb + 1], al[0], al[1], al[2], al[3], kh[nb][2], kh[nb][3]);
            }
            #pragma unroll
            for (int nb = 0; nb < 4; nb++) {
                mma16816(sacc[2 * nb],     ah[0], ah[1], ah[2], ah[3], kl[nb][0], kl[nb][1]);
                mma16816(sacc[2 * nb + 1], ah[0], ah[1], ah[2], ah[3], kl[nb][2], kl[nb][3]);
            }
        }

        #pragma unroll
        for (int nf = 0; nf < 8; nf++)
            #pragma unroll
            for (int q = 0; q < 4; q++) sacc[nf][q] *= scale;

        if (st == qt) {
            int lr0 = w * 16 + (lane >> 2);
            #pragma unroll
            for (int nf = 0; nf < 8; nf++) {
                #pragma unroll
                for (int q = 0; q < 4; q++) {
                    int col = nf * 8 + (lane & 3) * 2 + (q & 1);
                    int row = lr0 + ((q >> 1) << 3);
                    if (col > row) sacc[nf][q] = -INFINITY;
                }
            }
        }

        float mx0 = -INFINITY, mx1 = -INFINITY;
        #pragma unroll
        for (int nf = 0; nf < 8; nf++) {
            mx0 = fmaxf(mx0, fmaxf(sacc[nf][0], sacc[nf][1]));
            mx1 = fmaxf(mx1, fmaxf(sacc[nf][2], sacc[nf][3]));
        }
        mx0 = fmaxf(mx0, __shfl_xor_sync(0xFFFFFFFFu, mx0, 1));
        mx0 = fmaxf(mx0, __shfl_xor_sync(0xFFFFFFFFu, mx0, 2));
        mx1 = fmaxf(mx1, __shfl_xor_sync(0xFFFFFFFFu, mx1, 1));
        mx1 = fmaxf(mx1, __shfl_xor_sync(0xFFFFFFFFu, mx1, 2));

        float mn0 = fmaxf(m0, mx0), mn1 = fmaxf(m1, mx1);
        float c0 = __expf(m0 - mn0), c1 = __expf(m1 - mn1);
        m0 = mn0; m1 = mn1;

        float rs0 = 0.f, rs1 = 0.f;
        #pragma unroll
        for (int nf = 0; nf < 8; nf++) {
            sacc[nf][0] = __expf(sacc[nf][0] - mn0); rs0 += sacc[nf][0];
            sacc[nf][1] = __expf(sacc[nf][1] - mn0); rs0 += sacc[nf][1];
            sacc[nf][2] = __expf(sacc[nf][2] - mn1); rs1 += sacc[nf][2];
            sacc[nf][3] = __expf(sacc[nf][3] - mn1); rs1 += sacc[nf][3];
        }
        rs0 += __shfl_xor_sync(0xFFFFFFFFu, rs0, 1);
        rs0 += __shfl_xor_sync(0xFFFFFFFFu, rs0, 2);
        rs1 += __shfl_xor_sync(0xFFFFFFFFu, rs1, 1);
        rs1 += __shfl_xor_sync(0xFFFFFFFFu, rs1, 2);
        l0 = l0 * c0 + rs0;
        l1 = l1 * c1 + rs1;

        #pragma unroll
        for (int nf = 0; nf < 8; nf++) {
            oacc[nf][0] *= c0; oacc[nf][1] *= c0;
            oacc[nf][2] *= c1; oacc[nf][3] *= c1;
        }

        #pragma unroll
        for (int ks = 0; ks < 4; ks++) {
            uint32_t ph[4], pl[4];
            #pragma unroll
            for (int half = 0; half < 2; half++) {
                int f = 2 * ks + half;
                uint32_t h0 = pack2(sacc[f][0], sacc[f][1]);
                uint32_t h1 = pack2(sacc[f][2], sacc[f][3]);
                ph[2 * half + 0] = h0;
                ph[2 * half + 1] = h1;
                pl[2 * half + 0] = pack2(sacc[f][0] - bf16lo_f(h0),
                                         sacc[f][1] - bf16hi_f(h0));
                pl[2 * half + 1] = pack2(sacc[f][2] - bf16lo_f(h1),
                                         sacc[f][3] - bf16hi_f(h1));
            }
            #pragma unroll
            for (int nb2 = 0; nb2 < 4; nb2++) {
                uint32_t voff = ((ks * 16 + v_row) * ATP + nb2 * 16 + v_col) * 2;
                uint32_t vh[4], vl[4];
                ldsm4t(vh[0], vh[1], vh[2], vh[3], sVh + voff);
                ldsm4t(vl[0], vl[1], vl[2], vl[3], sVl + voff);
                mma16816(oacc[2 * nb2],     ph[0], ph[1], ph[2], ph[3], vh[0], vh[1]);
                mma16816(oacc[2 * nb2 + 1], ph[0], ph[1], ph[2], ph[3], vh[2], vh[3]);
                mma16816(oacc[2 * nb2],     pl[0], pl[1], pl[2], pl[3], vh[0], vh[1]);
                mma16816(oacc[2 * nb2 + 1], pl[0], pl[1], pl[2], pl[3], vh[2], vh[3]);
                mma16816(oacc[2 * nb2],     ph[0], ph[1], ph[2], ph[3], vl[0], vl[1]);
                mma16816(oacc[2 * nb2 + 1], ph[0], ph[1], ph[2], ph[3], vl[2], vl[3]);
            }
        }
    }

    float i0 = 1.0f / l0, i1 = 1.0f / l1;
    int row0 = q0 + w * 16 + (lane >> 2);
    #pragma unroll
    for (int nf = 0; nf < 8; nf++) {
        int col = hoff + nf * 8 + (lane & 3) * 2;
        size_t o0 = (tokbase + row0) * CDIM + col;
        size_t o1 = (tokbase + row0 + 8) * CDIM + col;
        union { __nv_bfloat16 b[2]; uint32_t u; } H, L;
        split1(oacc[nf][0] * i0, H.b[0], L.b[0]);
        split1(oacc[nf][1] * i0, H.b[1], L.b[1]);
        *(uint32_t*)(ohi + o0) = H.u;
        *(uint32_t*)(olo + o0) = L.u;
        split1(oacc[nf][2] * i1, H.b[0], L.b[0]);
        split1(oacc[nf][3] * i1, H.b[1], L.b[1]);
        *(uint32_t*)(ohi + o1) = H.u;
        *(uint32_t*)(olo + o1) = L.u;
    }
}

// ---------------- launch ------------------------------------------------------
extern "C" void kernel_launch(void* const* d_in, const int* in_sizes, int n_in,
                              void* d_out, int out_size) {
    const float* x    = (const float*)d_in[0];
    const float* Wq   = (const float*)d_in[1];
    const float* bq   = (const float*)d_in[2];
    const float* Wk   = (const float*)d_in[3];
    const float* bk   = (const float*)d_in[4];
    const float* Wv   = (const float*)d_in[5];
    const float* bv   = (const float*)d_in[6];
    const float* Wp   = (const float*)d_in[7];
    const float* bp   = (const float*)d_in[8];
    const float* W1   = (const float*)d_in[9];
    const float* b1   = (const float*)d_in[10];
    const float* W2   = (const float*)d_in[11];
    const float* b2   = (const float*)d_in[12];
    const float* ln1g = (const float*)d_in[13];
    const float* ln1b = (const float*)d_in[14];
    const float* ln2g = (const float*)d_in[15];
    const float* ln2b = (const float*)d_in[16];

    float *x2, *bqkv;
    __nv_bfloat16 *qkvh, *qkvl, *ahi, *alo, *f1hi, *f1lo;
    __nv_bfloat16 *wqh, *wql, *wph, *wpl, *w1h, *w1l, *w2h, *w2l;
    cudaGetSymbolAddress((void**)&qkvh, g_qkvhi);
    cudaGetSymbolAddress((void**)&qkvl, g_qkvlo);
    cudaGetSymbolAddress((void**)&x2,   g_x2);
    cudaGetSymbolAddress((void**)&bqkv, g_bqkv);
    cudaGetSymbolAddress((void**)&ahi,  g_ahi);
    cudaGetSymbolAddress((void**)&alo,  g_alo);
    cudaGetSymbolAddress((void**)&f1hi, g_f1hi);
    cudaGetSymbolAddress((void**)&f1lo, g_f1lo);
    cudaGetSymbolAddress((void**)&wqh,  g_wqkvhi);
    cudaGetSymbolAddress((void**)&wql,  g_wqkvlo);
    cudaGetSymbolAddress((void**)&wph,  g_wphi);
    cudaGetSymbolAddress((void**)&wpl,  g_wplo);
    cudaGetSymbolAddress((void**)&w1h,  g_w1hi);
    cudaGetSymbolAddress((void**)&w1l,  g_w1lo);
    cudaGetSymbolAddress((void**)&w2h,  g_w2hi);
    cudaGetSymbolAddress((void**)&w2l,  g_w2lo);

    const int attn_smem = 6 * 64 * ATP * (int)sizeof(__nv_bfloat16);  // 55296
    cudaFuncSetAttribute(fattn_mma_kernel,
                         cudaFuncAttributeMaxDynamicSharedMemorySize, attn_smem);
    cudaFuncSetAttribute(gemm_mma_kernel<false, false, true>,
                         cudaFuncAttributeMaxDynamicSharedMemorySize, GSMEM);
    cudaFuncSetAttribute(gemm_mma_kernel<false, true, false>,
                         cudaFuncAttributeMaxDynamicSharedMemorySize, GSMEM);
    cudaFuncSetAttribute(gemm_mma_kernel<true, false, true>,
                         cudaFuncAttributeMaxDynamicSharedMemorySize, GSMEM);

    // weight conversions
    wsplit_qkv_kernel<<<(QKVN * CDIM + 255) / 256, 256>>>(Wq, Wk, Wv, bq, bk, bv,
                                                          wqh, wql, bqkv);
    {
        dim3 grid((CDIM * CDIM + 255) / 256, 3);
        wsplit_t3_kernel<<<grid, 256>>>(Wp, W1, W2, wph, wpl, w1h, w1l, w2h, w2l);
    }

    // LN1 -> bf16 hi/lo
    ln_split_kernel<<<BT, 128>>>(x, ln1g, ln1b, ahi, alo);

    // QKV projection -> bf16 hi/lo
    {
        dim3 grid(QKVN / BN, BT / BM);
        gemm_mma_kernel<false, false, true><<<grid, 256, GSMEM>>>(
            QKVN, ahi, alo, wqh, wql, bqkv, nullptr, nullptr, qkvh, qkvl);
    }
    // HMMA flash attention -> bf16 hi/lo (reuses ahi/alo)
    {
        dim3 grid(SEQ / 64, BATCH * NH);
        fattn_mma_kernel<<<grid, 128, attn_smem>>>(qkvh, qkvl, ahi, alo);
    }
    // output projection + residual(x) -> x2 fp32
    {
        dim3 grid(CDIM / BN, BT / BM);
        gemm_mma_kernel<false, true, false><<<grid, 256, GSMEM>>>(
            CDIM, ahi, alo, wph, wpl, bp, x, x2, nullptr, nullptr);
        // LN2 -> bf16 hi/lo
        ln_split_kernel<<<BT, 128>>>(x2, ln2g, ln2b, ahi, alo);
        // FF1 + ReLU -> bf16 hi/lo
        gemm_mma_kernel<true, false, true><<<grid, 256, GSMEM>>>(
            CDIM, ahi, alo, w1h, w1l, b1, nullptr, nullptr, f1hi, f1lo);
        // FF2 + residual(x2) -> d_out fp32
        gemm_mma_kernel<false, true, false><<<grid, 256, GSMEM>>>(
            CDIM, f1hi, f1lo, w2h, w2l, b2, x2, (float*)d_out, nullptr, nullptr);
    }
}